// round 11
// baseline (speedup 1.0000x reference)
#include <cuda_runtime.h>
#include <cuda_bf16.h>
#include <math.h>
#include <cstdint>

#define Nn 64
#define Tt 512
#define Dd 128
#define Hh 256
#define G4 1024
#define TC 512
#define ROWS (Nn*Tt)

// ================= static scratch =================
__device__ float g_gatesF[(size_t)ROWS * G4];
__device__ float g_gatesB[(size_t)ROWS * G4];
__device__ float g_hs1[(size_t)ROWS * TC];
__device__ float g_scores[(size_t)Nn * Tt * Tt];
__device__ float g_cat[(size_t)ROWS * 1024];
__device__ float g_fc1[(size_t)ROWS * 50];
__device__ float g_fc2[(size_t)ROWS * 25];
__device__ float g_fc3[(size_t)ROWS * 10];
__device__ float g_mean[64];
__device__ float g_istd[64];
__device__ unsigned g_bcnt[2][64];
__device__ volatile unsigned g_bgen[2][64];

// h state as split bf16 [hi(256)|lo(256)] per batch row; double buffered, per dir
__device__ __align__(16) __nv_bfloat16 g_hsplit[2][2][Nn * 512];

// bf16 split buffers (K' = 3K)
__device__ __align__(16) __nv_bfloat16 g_xA[(size_t)ROWS * 384];
__device__ __align__(16) __nv_bfloat16 g_w0fB[(size_t)G4 * 384];
__device__ __align__(16) __nv_bfloat16 g_w0bB[(size_t)G4 * 384];
__device__ __align__(16) __nv_bfloat16 g_w1fB[(size_t)G4 * 1536];
__device__ __align__(16) __nv_bfloat16 g_w1bB[(size_t)G4 * 1536];
__device__ __align__(16) __nv_bfloat16 g_hs0A[(size_t)ROWS * 1536];
__device__ __align__(16) __nv_bfloat16 g_hs1A[(size_t)ROWS * 1536];
__device__ __align__(16) __nv_bfloat16 g_hs1B[(size_t)ROWS * 1536];
__device__ __align__(16) __nv_bfloat16 g_hsTB[(size_t)ROWS * 1536];
__device__ __align__(16) __nv_bfloat16 g_attnA[(size_t)ROWS * 1536];

// ================= per-direction grid barrier (64 CTAs each) =================
__device__ __forceinline__ void grid_sync_dir(int dir) {
    __syncthreads();
    if (threadIdx.x == 0) {
        __threadfence();
        unsigned gen = g_bgen[dir][0];
        if (atomicAdd(&g_bcnt[dir][0], 1) == 63) {
            g_bcnt[dir][0] = 0;
            __threadfence();
            g_bgen[dir][0] = gen + 1;
        } else {
            while (g_bgen[dir][0] == gen) { }
        }
    }
    __syncthreads();
}

// ================= HMMA helpers =================
__device__ __forceinline__ uint32_t smem_u32(const void* p) {
    uint32_t a;
    asm("{ .reg .u64 t; cvta.to.shared.u64 t, %1; cvt.u32.u64 %0, t; }" : "=r"(a) : "l"(p));
    return a;
}
__device__ __forceinline__ void ldsm_x4(uint32_t& r0, uint32_t& r1, uint32_t& r2, uint32_t& r3,
                                        uint32_t addr) {
    asm volatile("ldmatrix.sync.aligned.m8n8.x4.shared.b16 {%0,%1,%2,%3}, [%4];"
                 : "=r"(r0), "=r"(r1), "=r"(r2), "=r"(r3) : "r"(addr));
}
__device__ __forceinline__ void ldsm_x2(uint32_t& r0, uint32_t& r1, uint32_t addr) {
    asm volatile("ldmatrix.sync.aligned.m8n8.x2.shared.b16 {%0,%1}, [%2];"
                 : "=r"(r0), "=r"(r1) : "r"(addr));
}
__device__ __forceinline__ void mma16816(float* c, const uint32_t* a, const uint32_t* b) {
    asm volatile(
        "mma.sync.aligned.m16n8k16.row.col.f32.bf16.bf16.f32 "
        "{%0,%1,%2,%3}, {%4,%5,%6,%7}, {%8,%9}, {%0,%1,%2,%3};"
        : "+f"(c[0]), "+f"(c[1]), "+f"(c[2]), "+f"(c[3])
        : "r"(a[0]), "r"(a[1]), "r"(a[2]), "r"(a[3]), "r"(b[0]), "r"(b[1]));
}

// ================= HMMA bf16 GEMM: C(MxN) = A(MxK')·B(NxK')^T =================
#define SMSTRIDE 72

__global__ __launch_bounds__(256)
void gemm_mma(const __nv_bfloat16* __restrict__ Ag, const __nv_bfloat16* __restrict__ Bg,
              const float* __restrict__ bias, float* __restrict__ Cg,
              int Kp, int ldc, long sA, long sB, long sC)
{
    __shared__ __nv_bfloat16 As[128 * SMSTRIDE];
    __shared__ __nv_bfloat16 Bs[128 * SMSTRIDE];

    int tid = threadIdx.x;
    int wid = tid >> 5, lane = tid & 31;
    int warp_m = wid & 1;
    int warp_n = wid >> 1;

    const __nv_bfloat16* A = Ag + (long)blockIdx.z * sA + (long)blockIdx.y * 128 * Kp;
    const __nv_bfloat16* B = Bg + (long)blockIdx.z * sB + (long)blockIdx.x * 128 * Kp;
    float* C = Cg + (long)blockIdx.z * sC;

    uint32_t aBase = smem_u32(As);
    uint32_t bBase = smem_u32(Bs);

    float acc[4][4][4];
#pragma unroll
    for (int mi = 0; mi < 4; mi++)
#pragma unroll
        for (int ni = 0; ni < 4; ni++)
#pragma unroll
            for (int q = 0; q < 4; q++) acc[mi][ni][q] = 0.f;

    int NC = Kp >> 6;
    for (int c = 0; c < NC; c++) {
#pragma unroll
        for (int p = 0; p < 4; p++) {
            int idx = tid + p * 256;
            int row = idx >> 3, cg = (idx & 7) * 8;
            int4 va = *(const int4*)(A + (long)row * Kp + c * 64 + cg);
            *(int4*)(As + row * SMSTRIDE + cg) = va;
            int4 vb = *(const int4*)(B + (long)row * Kp + c * 64 + cg);
            *(int4*)(Bs + row * SMSTRIDE + cg) = vb;
        }
        __syncthreads();

#pragma unroll
        for (int kk = 0; kk < 4; kk++) {
            int k0 = kk * 16;
            uint32_t af[4][4], bfr[4][2];
#pragma unroll
            for (int mi = 0; mi < 4; mi++) {
                int row = warp_m * 64 + mi * 16 + (lane & 15);
                int col = k0 + (lane >> 4) * 8;
                ldsm_x4(af[mi][0], af[mi][1], af[mi][2], af[mi][3],
                        aBase + (row * SMSTRIDE + col) * 2);
            }
#pragma unroll
            for (int ni = 0; ni < 4; ni++) {
                int row = warp_n * 32 + ni * 8 + (lane & 7);
                int col = k0 + ((lane >> 3) & 1) * 8;
                ldsm_x2(bfr[ni][0], bfr[ni][1], bBase + (row * SMSTRIDE + col) * 2);
            }
#pragma unroll
            for (int mi = 0; mi < 4; mi++)
#pragma unroll
                for (int ni = 0; ni < 4; ni++)
                    mma16816(acc[mi][ni], af[mi], bfr[ni]);
        }
        __syncthreads();
    }

    int m_base = blockIdx.y * 128 + warp_m * 64;
    int n_base = blockIdx.x * 128 + warp_n * 32;
    int r = lane >> 2, cp = (lane & 3) * 2;
#pragma unroll
    for (int mi = 0; mi < 4; mi++) {
#pragma unroll
        for (int ni = 0; ni < 4; ni++) {
            int m = m_base + mi * 16 + r;
            int n = n_base + ni * 8 + cp;
            float2 v0 = make_float2(acc[mi][ni][0], acc[mi][ni][1]);
            float2 v1 = make_float2(acc[mi][ni][2], acc[mi][ni][3]);
            if (bias) {
                float b0 = bias[n], b1 = bias[n + 1];
                v0.x += b0; v0.y += b1;
                v1.x += b0; v1.y += b1;
            }
            *(float2*)(C + (long)m * ldc + n) = v0;
            *(float2*)(C + (long)(m + 8) * ldc + n) = v1;
        }
    }
}

// ================= split-bf16 conversion =================
__global__ void conv_split(const float* __restrict__ src, __nv_bfloat16* __restrict__ dst,
                           int kshift, long total, int flavB)
{
    long i = (long)blockIdx.x * blockDim.x + threadIdx.x;
    if (i >= total) return;
    int K = 1 << kshift;
    long m = i >> kshift;
    int k = (int)(i & (K - 1));
    float x = src[i];
    __nv_bfloat16 hi = __float2bfloat16_rn(x);
    __nv_bfloat16 lo = __float2bfloat16_rn(x - __bfloat162float(hi));
    __nv_bfloat16* d = dst + m * 3 * K;
    d[k] = hi;
    if (flavB) { d[K + k] = lo; d[2 * K + k] = hi; }
    else       { d[K + k] = hi; d[2 * K + k] = lo; }
}

__global__ void transp_convB(const float* __restrict__ hs, __nv_bfloat16* __restrict__ dst)
{
    __shared__ float tile[32][33];
    int n = blockIdx.z;
    int s0 = blockIdx.y * 32, h0 = blockIdx.x * 32;
    int tx = threadIdx.x, ty = threadIdx.y;
    tile[ty][tx] = hs[((long)n * Tt + s0 + ty) * TC + h0 + tx];
    __syncthreads();
    float x = tile[tx][ty];
    __nv_bfloat16 hi = __float2bfloat16_rn(x);
    __nv_bfloat16 lo = __float2bfloat16_rn(x - __bfloat162float(hi));
    __nv_bfloat16* d = dst + (long)n * Tt * 1536 + (long)(h0 + ty) * 1536;
    int s = s0 + tx;
    d[s] = hi; d[512 + s] = lo; d[1024 + s] = hi;
}

// ================= persistent LSTM with HMMA recurrence (R8 layout) =================
// 128 CTAs: dir (2) x 64 column-slices. Each CTA: M=64 batch rows, N=16
// gate-interleaved cols (4 units x 4 gates), K'=768 (3-term split).
// 8 warps = 4 M-slices x 2 K-halves. B frags (24 x 4 regs) loop-invariant.
// Epilogue writes split-bf16 outputs DIRECTLY (fused conversion):
//   hsA (flavor A), optional hsB (flavor B), optional hsF (fp32).
#define AS_STR 520
#define BS_STR 776
#define LSTM2_SMEM (64 * AS_STR * 2 + 16 * BS_STR * 2 + 3 * 64 * 16 * 4)

__global__ __launch_bounds__(256, 1)
void lstm_mma(const float* __restrict__ gatesF, const float* __restrict__ gatesB,
              const float* __restrict__ whhF, const float* __restrict__ whhB,
              __nv_bfloat16* __restrict__ hsA, __nv_bfloat16* __restrict__ hsB,
              float* __restrict__ hsF)
{
    extern __shared__ char smraw[];
    __nv_bfloat16* As = (__nv_bfloat16*)smraw;
    __nv_bfloat16* Bs = As + 64 * AS_STR;
    float* gsm   = (float*)(Bs + 16 * BS_STR);
    float* ssum0 = gsm + 64 * 16;
    float* ssum1 = ssum0 + 64 * 16;

    int bx = blockIdx.x;
    int dir  = bx >> 6;
    int cidx = bx & 63;
    int jbase = cidx * 4;
    int tid = threadIdx.x;
    int wid = tid >> 5, lane = tid & 31;

    const float* W     = dir ? whhB : whhF;
    const float* gates = dir ? gatesB : gatesF;

    for (int i = tid; i < 16 * 768; i += 256) {
        int r = i / 768, k = i - r * 768;
        int j = jbase + (r >> 2);
        int g = r & 3;
        int korig = k & 255;
        float w = W[((long)(g * Hh + j)) * Hh + korig];
        __nv_bfloat16 hi = __float2bfloat16_rn(w);
        __nv_bfloat16 v;
        if (k >= 256 && k < 512) v = __float2bfloat16_rn(w - __bfloat162float(hi));
        else v = hi;
        Bs[r * BS_STR + k] = v;
    }
    __syncthreads();

    uint32_t aB = smem_u32(As);
    uint32_t bB = smem_u32(Bs);
    int wm = (wid & 3) * 16;
    int kh = wid >> 2;
    float* sdst = kh ? ssum1 : ssum0;

    uint32_t breg[24][4];
#pragma unroll
    for (int si = 0; si < 24; si++) {
        int s = kh * 24 + si;
        int rowB = (lane & 7) + ((lane >> 4) << 3);
        int colB = s * 16 + (((lane >> 3) & 1) << 3);
        ldsm_x4(breg[si][0], breg[si][1], breg[si][2], breg[si][3],
                bB + (rowB * BS_STR + colB) * 2);
    }

    int b = tid >> 2, jj = tid & 3;
    {
        __nv_bfloat16 z = __float2bfloat16_rn(0.f);
        g_hsplit[0][dir][b * 512 + jbase + jj] = z;
        g_hsplit[0][dir][b * 512 + 256 + jbase + jj] = z;
    }
    float c = 0.f;
    grid_sync_dir(dir);

    for (int t = 0; t < Tt; t++) {
        const __nv_bfloat16* hin = g_hsplit[t & 1][dir];
        int tin = dir ? (Tt - 1 - t) : t;

        const int4* src = (const int4*)hin;
#pragma unroll
        for (int i = 0; i < 16; i++) {
            int idx = tid + i * 256;
            int row = idx >> 6, ch = idx & 63;
            int4 v = __ldcg(src + row * 64 + ch);
            *(int4*)(As + row * AS_STR + ch * 8) = v;
        }
        {
            int g = tid & 3;
            float4 gv = __ldg((const float4*)(gates + ((long)b * Tt + tin) * G4 + g * Hh + jbase));
            gsm[b * 16 + 0  + g] = gv.x;
            gsm[b * 16 + 4  + g] = gv.y;
            gsm[b * 16 + 8  + g] = gv.z;
            gsm[b * 16 + 12 + g] = gv.w;
        }
        __syncthreads();

        float acc0[4] = {0.f, 0.f, 0.f, 0.f};
        float acc1[4] = {0.f, 0.f, 0.f, 0.f};
#pragma unroll
        for (int si = 0; si < 24; si++) {
            int s = kh * 24 + si;
            int kc = (s < 32) ? (s & 15) * 16 : 256 + (s - 32) * 16;
            uint32_t af[4];
            ldsm_x4(af[0], af[1], af[2], af[3],
                    aB + ((wm + (lane & 15)) * AS_STR + kc + (lane >> 4) * 8) * 2);
            uint32_t bf0[2] = {breg[si][0], breg[si][1]};
            uint32_t bf1[2] = {breg[si][2], breg[si][3]};
            mma16816(acc0, af, bf0);
            mma16816(acc1, af, bf1);
        }

        {
            int r = lane >> 2, cp = (lane & 3) * 2;
            int m1 = wm + r, m2 = wm + r + 8;
            *(float2*)&sdst[m1 * 16 + cp]     = make_float2(acc0[0], acc0[1]);
            *(float2*)&sdst[m2 * 16 + cp]     = make_float2(acc0[2], acc0[3]);
            *(float2*)&sdst[m1 * 16 + 8 + cp] = make_float2(acc1[0], acc1[1]);
            *(float2*)&sdst[m2 * 16 + 8 + cp] = make_float2(acc1[2], acc1[3]);
        }
        __syncthreads();

        int base = b * 16 + jj * 4;
        float gi = gsm[base + 0] + ssum0[base + 0] + ssum1[base + 0];
        float gf = gsm[base + 1] + ssum0[base + 1] + ssum1[base + 1];
        float gg = gsm[base + 2] + ssum0[base + 2] + ssum1[base + 2];
        float go = gsm[base + 3] + ssum0[base + 3] + ssum1[base + 3];

        float ii = 1.f / (1.f + expf(-gi));
        float ff = 1.f / (1.f + expf(-gf));
        float tg = tanhf(gg);
        float oo = 1.f / (1.f + expf(-go));
        c = ff * c + ii * tg;
        float h = oo * tanhf(c);

        __nv_bfloat16 hi = __float2bfloat16_rn(h);
        __nv_bfloat16 lo = __float2bfloat16_rn(h - __bfloat162float(hi));
        __nv_bfloat16* hnext = g_hsplit[(t + 1) & 1][dir];
        hnext[b * 512 + jbase + jj] = hi;
        hnext[b * 512 + 256 + jbase + jj] = lo;

        // fused split-format outputs
        long m = (long)b * Tt + tin;
        int hcol = dir * Hh + jbase + jj;
        __nv_bfloat16* dA = hsA + m * 1536;
        dA[hcol] = hi; dA[512 + hcol] = hi; dA[1024 + hcol] = lo;
        if (hsB) {
            __nv_bfloat16* dB = hsB + m * 1536;
            dB[hcol] = hi; dB[512 + hcol] = lo; dB[1024 + hcol] = hi;
        }
        if (hsF) hsF[m * TC + hcol] = h;

        grid_sync_dir(dir);
    }
}

// ================= misc =================
__global__ void copy_right(const float* __restrict__ hs, float* __restrict__ cat) {
    long i = (long)blockIdx.x * blockDim.x + threadIdx.x;
    if (i < (long)ROWS * TC) {
        long m = i / TC, j = i % TC;
        cat[m * 1024 + 512 + j] = hs[i];
    }
}

__global__ void softmax_rows(const float* __restrict__ S, __nv_bfloat16* __restrict__ dst) {
    const float* row = S + (long)blockIdx.x * Tt;
    __nv_bfloat16* d = dst + (long)blockIdx.x * 1536;
    int tid = threadIdx.x;   // 128
    __shared__ float red[4];

    float mx = -1e30f;
    for (int j = tid; j < Tt; j += 128) mx = fmaxf(mx, row[j]);
#pragma unroll
    for (int o = 16; o; o >>= 1) mx = fmaxf(mx, __shfl_xor_sync(0xffffffffu, mx, o));
    if ((tid & 31) == 0) red[tid >> 5] = mx;
    __syncthreads();
    mx = fmaxf(fmaxf(red[0], red[1]), fmaxf(red[2], red[3]));

    float sum = 0.f;
    float e[4];
#pragma unroll
    for (int q = 0; q < 4; q++) {
        e[q] = expf(row[tid + q * 128] - mx);
        sum += e[q];
    }
#pragma unroll
    for (int o = 16; o; o >>= 1) sum += __shfl_xor_sync(0xffffffffu, sum, o);
    __syncthreads();
    if ((tid & 31) == 0) red[tid >> 5] = sum;
    __syncthreads();
    sum = red[0] + red[1] + red[2] + red[3];
    float inv = 1.f / sum;
#pragma unroll
    for (int q = 0; q < 4; q++) {
        int jj = tid + q * 128;
        float p = e[q] * inv;
        __nv_bfloat16 hi = __float2bfloat16_rn(p);
        __nv_bfloat16 lo = __float2bfloat16_rn(p - __bfloat162float(hi));
        d[jj] = hi; d[512 + jj] = hi; d[1024 + jj] = lo;
    }
}

__global__ void bn_stats(const float* __restrict__ Y, float* __restrict__ mean,
                         float* __restrict__ istd) {
    int ch = blockIdx.x;
    int tid = threadIdx.x;
    __shared__ float rs[8], rq[8];
    float s = 0.f, q = 0.f;
    for (int i = tid; i < Nn * Tt; i += 256) {
        int n = i >> 9, p = i & 511;
        float v = Y[(long)n * 25600 + ch * 512 + p];
        s += v; q += v * v;
    }
#pragma unroll
    for (int o = 16; o; o >>= 1) { s += __shfl_xor_sync(0xffffffffu, s, o); q += __shfl_xor_sync(0xffffffffu, q, o); }
    if ((tid & 31) == 0) { rs[tid >> 5] = s; rq[tid >> 5] = q; }
    __syncthreads();
    if (tid == 0) {
        s = 0.f; q = 0.f;
        for (int w = 0; w < 8; w++) { s += rs[w]; q += rq[w]; }
        float m = s / (float)(Nn * Tt);
        float var = q / (float)(Nn * Tt) - m * m;
        mean[ch] = m;
        istd[ch] = rsqrtf(var + 1e-5f);
    }
}

__global__ void bn_apply(float* __restrict__ Y, const float* __restrict__ mean,
                         const float* __restrict__ istd, const float* __restrict__ gam,
                         const float* __restrict__ bet) {
    long i = (long)blockIdx.x * blockDim.x + threadIdx.x;
    if (i < (long)ROWS * 50) {
        long r = i % 25600;
        int ch = (int)(r >> 9);
        Y[i] = (Y[i] - mean[ch]) * istd[ch] * gam[ch] + bet[ch];
    }
}

// fc1: fp32 64x64 tile GEMM (measured cheaper than HMMA+conversion for N=50)
__global__ void gemm_bt64(const float* __restrict__ A, const float* __restrict__ B,
                          const float* __restrict__ bias, float* __restrict__ C,
                          int M, int N, int K, int ldc, int relu)
{
    __shared__ float As[16][64];
    __shared__ float Bs[16][64];
    int tx = threadIdx.x, ty = threadIdx.y;
    int tid = ty * 16 + tx;
    int m0 = blockIdx.y * 64, n0 = blockIdx.x * 64;

    float acc[4][4];
#pragma unroll
    for (int i = 0; i < 4; i++)
#pragma unroll
        for (int j = 0; j < 4; j++) acc[i][j] = 0.f;

    int lrow = tid >> 2;
    int lk   = (tid & 3) * 4;

    for (int k0 = 0; k0 < K; k0 += 16) {
        {
            float4 v = make_float4(0.f, 0.f, 0.f, 0.f);
            int m = m0 + lrow;
            if (m < M) v = *(const float4*)(A + (long)m * K + k0 + lk);
            As[lk + 0][lrow] = v.x; As[lk + 1][lrow] = v.y;
            As[lk + 2][lrow] = v.z; As[lk + 3][lrow] = v.w;
        }
        {
            float4 v = make_float4(0.f, 0.f, 0.f, 0.f);
            int n = n0 + lrow;
            if (n < N) v = *(const float4*)(B + (long)n * K + k0 + lk);
            Bs[lk + 0][lrow] = v.x; Bs[lk + 1][lrow] = v.y;
            Bs[lk + 2][lrow] = v.z; Bs[lk + 3][lrow] = v.w;
        }
        __syncthreads();
#pragma unroll
        for (int kk = 0; kk < 16; kk++) {
            float4 a = *(const float4*)&As[kk][ty * 4];
            float4 b = *(const float4*)&Bs[kk][tx * 4];
            acc[0][0] += a.x * b.x; acc[0][1] += a.x * b.y; acc[0][2] += a.x * b.z; acc[0][3] += a.x * b.w;
            acc[1][0] += a.y * b.x; acc[1][1] += a.y * b.y; acc[1][2] += a.y * b.z; acc[1][3] += a.y * b.w;
            acc[2][0] += a.z * b.x; acc[2][1] += a.z * b.y; acc[2][2] += a.z * b.z; acc[2][3] += a.z * b.w;
            acc[3][0] += a.w * b.x; acc[3][1] += a.w * b.y; acc[3][2] += a.w * b.z; acc[3][3] += a.w * b.w;
        }
        __syncthreads();
    }
#pragma unroll
    for (int i = 0; i < 4; i++) {
        int m = m0 + ty * 4 + i;
        if (m >= M) continue;
#pragma unroll
        for (int j = 0; j < 4; j++) {
            int n = n0 + tx * 4 + j;
            if (n >= N) continue;
            float v = acc[i][j];
            if (bias) v += bias[n];
            if (relu) v = fmaxf(v, 0.f);
            C[(long)m * ldc + n] = v;
        }
    }
}

template <int K, int N, bool RELU>
__global__ void small_fc(const float* __restrict__ X, const float* __restrict__ W,
                         const float* __restrict__ bias, float* __restrict__ Y) {
    __shared__ float xs[128 * K];
    __shared__ float ws[N * K];
    __shared__ float bs[N];
    int tid = threadIdx.x;
    long m0 = (long)blockIdx.x * 128;
    for (int i = tid; i < N * K; i += 128) ws[i] = W[i];
    for (int i = tid; i < N; i += 128) bs[i] = bias[i];
    for (int i = tid; i < 128 * K; i += 128) xs[i] = X[m0 * K + i];
    __syncthreads();
    long m = m0 + tid;
#pragma unroll
    for (int j = 0; j < N; j++) {
        float acc = bs[j];
#pragma unroll
        for (int k = 0; k < K; k++) acc += xs[tid * K + k] * ws[j * K + k];
        if (RELU) acc = fmaxf(acc, 0.f);
        Y[m * N + j] = acc;
    }
}

// ================= host orchestration =================
extern "C" void kernel_launch(void* const* d_in, const int* in_sizes, int n_in,
                              void* d_out, int out_size)
{
    const float* x     = (const float*)d_in[0];
    const float* wih0f = (const float*)d_in[1];
    const float* whh0f = (const float*)d_in[2];
    const float* b0f   = (const float*)d_in[3];
    const float* wih0b = (const float*)d_in[4];
    const float* whh0b = (const float*)d_in[5];
    const float* b0b   = (const float*)d_in[6];
    const float* wih1f = (const float*)d_in[7];
    const float* whh1f = (const float*)d_in[8];
    const float* b1f   = (const float*)d_in[9];
    const float* wih1b = (const float*)d_in[10];
    const float* whh1b = (const float*)d_in[11];
    const float* b1b   = (const float*)d_in[12];
    const float* fc1w  = (const float*)d_in[13];
    const float* fc1b  = (const float*)d_in[14];
    const float* bng   = (const float*)d_in[15];
    const float* bnb   = (const float*)d_in[16];
    const float* fc2w  = (const float*)d_in[17];
    const float* fc2b  = (const float*)d_in[18];
    const float* fc3w  = (const float*)d_in[19];
    const float* fc3b  = (const float*)d_in[20];
    const float* fc4w  = (const float*)d_in[21];
    const float* fc4b  = (const float*)d_in[22];
    float* out = (float*)d_out;

    float *gF, *gB, *hs1, *sc, *cat, *f1, *f2, *f3, *mean, *istd;
    __nv_bfloat16 *xA, *w0fB, *w0bB, *w1fB, *w1bB, *hs0A, *hs1A, *hs1B, *hsTB, *attnA;
    cudaGetSymbolAddress((void**)&gF,   g_gatesF);
    cudaGetSymbolAddress((void**)&gB,   g_gatesB);
    cudaGetSymbolAddress((void**)&hs1,  g_hs1);
    cudaGetSymbolAddress((void**)&sc,   g_scores);
    cudaGetSymbolAddress((void**)&cat,  g_cat);
    cudaGetSymbolAddress((void**)&f1,   g_fc1);
    cudaGetSymbolAddress((void**)&f2,   g_fc2);
    cudaGetSymbolAddress((void**)&f3,   g_fc3);
    cudaGetSymbolAddress((void**)&mean, g_mean);
    cudaGetSymbolAddress((void**)&istd, g_istd);
    cudaGetSymbolAddress((void**)&xA,    g_xA);
    cudaGetSymbolAddress((void**)&w0fB,  g_w0fB);
    cudaGetSymbolAddress((void**)&w0bB,  g_w0bB);
    cudaGetSymbolAddress((void**)&w1fB,  g_w1fB);
    cudaGetSymbolAddress((void**)&w1bB,  g_w1bB);
    cudaGetSymbolAddress((void**)&hs0A,  g_hs0A);
    cudaGetSymbolAddress((void**)&hs1A,  g_hs1A);
    cudaGetSymbolAddress((void**)&hs1B,  g_hs1B);
    cudaGetSymbolAddress((void**)&hsTB,  g_hsTB);
    cudaGetSymbolAddress((void**)&attnA, g_attnA);

    cudaFuncSetAttribute(lstm_mma, cudaFuncAttributeMaxDynamicSharedMemorySize, LSTM2_SMEM);

    // ---- conversions (weights + input only; hs conversions fused into LSTM) ----
    conv_split<<<(int)(((long)ROWS * Dd + 255) / 256), 256>>>(x, xA, 7, (long)ROWS * Dd, 0);
    conv_split<<<(G4 * Dd + 255) / 256, 256>>>(wih0f, w0fB, 7, (long)G4 * Dd, 1);
    conv_split<<<(G4 * Dd + 255) / 256, 256>>>(wih0b, w0bB, 7, (long)G4 * Dd, 1);
    conv_split<<<(G4 * TC + 255) / 256, 256>>>(wih1f, w1fB, 9, (long)G4 * TC, 1);
    conv_split<<<(G4 * TC + 255) / 256, 256>>>(wih1b, w1bB, 9, (long)G4 * TC, 1);

    // ---- layer 0 (writes hs0A split directly) ----
    gemm_mma<<<dim3(8, 256), 256>>>(xA, w0fB, b0f, gF, 384, G4, 0, 0, 0);
    gemm_mma<<<dim3(8, 256), 256>>>(xA, w0bB, b0b, gB, 384, G4, 0, 0, 0);
    lstm_mma<<<128, 256, LSTM2_SMEM>>>(gF, gB, whh0f, whh0b, hs0A, nullptr, nullptr);

    // ---- layer 1 (writes hs1 fp32 + hs1A + hs1B directly) ----
    gemm_mma<<<dim3(8, 256), 256>>>(hs0A, w1fB, b1f, gF, 1536, G4, 0, 0, 0);
    gemm_mma<<<dim3(8, 256), 256>>>(hs0A, w1bB, b1b, gB, 1536, G4, 0, 0, 0);
    lstm_mma<<<128, 256, LSTM2_SMEM>>>(gF, gB, whh1f, whh1b, hs1A, hs1B, hs1);

    // ---- attention ----
    transp_convB<<<dim3(16, 16, Nn), dim3(32, 32)>>>(hs1, hsTB);

    long sAB = (long)Tt * 1536;
    gemm_mma<<<dim3(4, 4, Nn), 256>>>(hs1A, hs1B, nullptr, sc, 1536, Tt,
                                      sAB, sAB, (long)Tt * Tt);
    softmax_rows<<<Nn * Tt, 128>>>(sc, attnA);
    gemm_mma<<<dim3(4, 4, Nn), 256>>>(attnA, hsTB, nullptr, cat, 1536, 1024,
                                      sAB, sAB, (long)Tt * 1024);
    copy_right<<<(int)(((long)ROWS * TC + 255) / 256), 256>>>(hs1, cat);

    // ---- head ----
    gemm_bt64<<<dim3(1, 512), dim3(16, 16)>>>(cat, fc1w, fc1b, f1, ROWS, 50, 1024, 50, 1);
    bn_stats<<<50, 256>>>(f1, mean, istd);
    bn_apply<<<(int)(((long)ROWS * 50 + 255) / 256), 256>>>(f1, mean, istd, bng, bnb);
    small_fc<50, 25, true ><<<ROWS / 128, 128>>>(f1, fc2w, fc2b, f2);
    small_fc<25, 10, true ><<<ROWS / 128, 128>>>(f2, fc3w, fc3b, f3);
    small_fc<10, 2,  false><<<ROWS / 128, 128>>>(f3, fc4w, fc4b, out);
}

// round 12
// speedup vs baseline: 1.1589x; 1.1589x over previous
#include <cuda_runtime.h>
#include <cuda_bf16.h>
#include <math.h>
#include <cstdint>

#define Nn 64
#define Tt 512
#define Dd 128
#define Hh 256
#define G4 1024
#define TC 512
#define ROWS (Nn*Tt)

// ================= static scratch =================
__device__ float g_gatesF[(size_t)ROWS * G4];
__device__ float g_gatesB[(size_t)ROWS * G4];
__device__ float g_hs0[(size_t)ROWS * TC];
__device__ float g_hs1[(size_t)ROWS * TC];
__device__ float g_scores[(size_t)Nn * Tt * Tt];
__device__ float g_cat[(size_t)ROWS * 1024];
__device__ float g_fc1[(size_t)ROWS * 50];
__device__ float g_fc2[(size_t)ROWS * 25];
__device__ float g_fc3[(size_t)ROWS * 10];
__device__ float g_mean[64];
__device__ float g_istd[64];
__device__ unsigned g_bcnt[2][64];
__device__ volatile unsigned g_bgen[2][64];

// h state as split bf16 [hi(256)|lo(256)] per batch row; double buffered, per dir
__device__ __align__(16) __nv_bfloat16 g_hsplit[2][2][Nn * 512];

// bf16 split buffers (K' = 3K)
__device__ __align__(16) __nv_bfloat16 g_xA[(size_t)ROWS * 384];
__device__ __align__(16) __nv_bfloat16 g_w0fB[(size_t)G4 * 384];
__device__ __align__(16) __nv_bfloat16 g_w0bB[(size_t)G4 * 384];
__device__ __align__(16) __nv_bfloat16 g_w1fB[(size_t)G4 * 1536];
__device__ __align__(16) __nv_bfloat16 g_w1bB[(size_t)G4 * 1536];
__device__ __align__(16) __nv_bfloat16 g_hs0A[(size_t)ROWS * 1536];
__device__ __align__(16) __nv_bfloat16 g_hs1A[(size_t)ROWS * 1536];
__device__ __align__(16) __nv_bfloat16 g_hs1B[(size_t)ROWS * 1536];
__device__ __align__(16) __nv_bfloat16 g_hsTB[(size_t)ROWS * 1536];
__device__ __align__(16) __nv_bfloat16 g_attnA[(size_t)ROWS * 1536];

// ================= per-direction grid barrier (64 CTAs each) =================
__device__ __forceinline__ void grid_sync_dir(int dir) {
    __syncthreads();
    if (threadIdx.x == 0) {
        __threadfence();
        unsigned gen = g_bgen[dir][0];
        if (atomicAdd(&g_bcnt[dir][0], 1) == 63) {
            g_bcnt[dir][0] = 0;
            __threadfence();
            g_bgen[dir][0] = gen + 1;
        } else {
            while (g_bgen[dir][0] == gen) { }
        }
    }
    __syncthreads();
}

// ================= HMMA helpers =================
__device__ __forceinline__ uint32_t smem_u32(const void* p) {
    uint32_t a;
    asm("{ .reg .u64 t; cvta.to.shared.u64 t, %1; cvt.u32.u64 %0, t; }" : "=r"(a) : "l"(p));
    return a;
}
__device__ __forceinline__ void ldsm_x4(uint32_t& r0, uint32_t& r1, uint32_t& r2, uint32_t& r3,
                                        uint32_t addr) {
    asm volatile("ldmatrix.sync.aligned.m8n8.x4.shared.b16 {%0,%1,%2,%3}, [%4];"
                 : "=r"(r0), "=r"(r1), "=r"(r2), "=r"(r3) : "r"(addr));
}
__device__ __forceinline__ void ldsm_x2(uint32_t& r0, uint32_t& r1, uint32_t addr) {
    asm volatile("ldmatrix.sync.aligned.m8n8.x2.shared.b16 {%0,%1}, [%2];"
                 : "=r"(r0), "=r"(r1) : "r"(addr));
}
__device__ __forceinline__ void mma16816(float* c, const uint32_t* a, const uint32_t* b) {
    asm volatile(
        "mma.sync.aligned.m16n8k16.row.col.f32.bf16.bf16.f32 "
        "{%0,%1,%2,%3}, {%4,%5,%6,%7}, {%8,%9}, {%0,%1,%2,%3};"
        : "+f"(c[0]), "+f"(c[1]), "+f"(c[2]), "+f"(c[3])
        : "r"(a[0]), "r"(a[1]), "r"(a[2]), "r"(a[3]), "r"(b[0]), "r"(b[1]));
}

// ================= HMMA bf16 GEMM: C(MxN) = A(MxK')·B(NxK')^T =================
#define SMSTRIDE 72

__global__ __launch_bounds__(256)
void gemm_mma(const __nv_bfloat16* __restrict__ Ag, const __nv_bfloat16* __restrict__ Bg,
              const float* __restrict__ bias, float* __restrict__ Cg,
              int Kp, int ldc, long sA, long sB, long sC)
{
    __shared__ __nv_bfloat16 As[128 * SMSTRIDE];
    __shared__ __nv_bfloat16 Bs[128 * SMSTRIDE];

    int tid = threadIdx.x;
    int wid = tid >> 5, lane = tid & 31;
    int warp_m = wid & 1;
    int warp_n = wid >> 1;

    const __nv_bfloat16* A = Ag + (long)blockIdx.z * sA + (long)blockIdx.y * 128 * Kp;
    const __nv_bfloat16* B = Bg + (long)blockIdx.z * sB + (long)blockIdx.x * 128 * Kp;
    float* C = Cg + (long)blockIdx.z * sC;

    uint32_t aBase = smem_u32(As);
    uint32_t bBase = smem_u32(Bs);

    float acc[4][4][4];
#pragma unroll
    for (int mi = 0; mi < 4; mi++)
#pragma unroll
        for (int ni = 0; ni < 4; ni++)
#pragma unroll
            for (int q = 0; q < 4; q++) acc[mi][ni][q] = 0.f;

    int NC = Kp >> 6;
    for (int c = 0; c < NC; c++) {
#pragma unroll
        for (int p = 0; p < 4; p++) {
            int idx = tid + p * 256;
            int row = idx >> 3, cg = (idx & 7) * 8;
            int4 va = *(const int4*)(A + (long)row * Kp + c * 64 + cg);
            *(int4*)(As + row * SMSTRIDE + cg) = va;
            int4 vb = *(const int4*)(B + (long)row * Kp + c * 64 + cg);
            *(int4*)(Bs + row * SMSTRIDE + cg) = vb;
        }
        __syncthreads();

#pragma unroll
        for (int kk = 0; kk < 4; kk++) {
            int k0 = kk * 16;
            uint32_t af[4][4], bfr[4][2];
#pragma unroll
            for (int mi = 0; mi < 4; mi++) {
                int row = warp_m * 64 + mi * 16 + (lane & 15);
                int col = k0 + (lane >> 4) * 8;
                ldsm_x4(af[mi][0], af[mi][1], af[mi][2], af[mi][3],
                        aBase + (row * SMSTRIDE + col) * 2);
            }
#pragma unroll
            for (int ni = 0; ni < 4; ni++) {
                int row = warp_n * 32 + ni * 8 + (lane & 7);
                int col = k0 + ((lane >> 3) & 1) * 8;
                ldsm_x2(bfr[ni][0], bfr[ni][1], bBase + (row * SMSTRIDE + col) * 2);
            }
#pragma unroll
            for (int mi = 0; mi < 4; mi++)
#pragma unroll
                for (int ni = 0; ni < 4; ni++)
                    mma16816(acc[mi][ni], af[mi], bfr[ni]);
        }
        __syncthreads();
    }

    int m_base = blockIdx.y * 128 + warp_m * 64;
    int n_base = blockIdx.x * 128 + warp_n * 32;
    int r = lane >> 2, cp = (lane & 3) * 2;
#pragma unroll
    for (int mi = 0; mi < 4; mi++) {
#pragma unroll
        for (int ni = 0; ni < 4; ni++) {
            int m = m_base + mi * 16 + r;
            int n = n_base + ni * 8 + cp;
            float2 v0 = make_float2(acc[mi][ni][0], acc[mi][ni][1]);
            float2 v1 = make_float2(acc[mi][ni][2], acc[mi][ni][3]);
            if (bias) {
                float b0 = bias[n], b1 = bias[n + 1];
                v0.x += b0; v0.y += b1;
                v1.x += b0; v1.y += b1;
            }
            *(float2*)(C + (long)m * ldc + n) = v0;
            *(float2*)(C + (long)(m + 8) * ldc + n) = v1;
        }
    }
}

// ================= split-bf16 conversion =================
__global__ void conv_split(const float* __restrict__ src, __nv_bfloat16* __restrict__ dst,
                           int kshift, long total, int flavB)
{
    long i = (long)blockIdx.x * blockDim.x + threadIdx.x;
    if (i >= total) return;
    int K = 1 << kshift;
    long m = i >> kshift;
    int k = (int)(i & (K - 1));
    float x = src[i];
    __nv_bfloat16 hi = __float2bfloat16_rn(x);
    __nv_bfloat16 lo = __float2bfloat16_rn(x - __bfloat162float(hi));
    __nv_bfloat16* d = dst + m * 3 * K;
    d[k] = hi;
    if (flavB) { d[K + k] = lo; d[2 * K + k] = hi; }
    else       { d[K + k] = hi; d[2 * K + k] = lo; }
}

__global__ void transp_convB(const float* __restrict__ hs, __nv_bfloat16* __restrict__ dst)
{
    __shared__ float tile[32][33];
    int n = blockIdx.z;
    int s0 = blockIdx.y * 32, h0 = blockIdx.x * 32;
    int tx = threadIdx.x, ty = threadIdx.y;
    tile[ty][tx] = hs[((long)n * Tt + s0 + ty) * TC + h0 + tx];
    __syncthreads();
    float x = tile[tx][ty];
    __nv_bfloat16 hi = __float2bfloat16_rn(x);
    __nv_bfloat16 lo = __float2bfloat16_rn(x - __bfloat162float(hi));
    __nv_bfloat16* d = dst + (long)n * Tt * 1536 + (long)(h0 + ty) * 1536;
    int s = s0 + tx;
    d[s] = hi; d[512 + s] = lo; d[1024 + s] = hi;
}

// ================= persistent LSTM with HMMA recurrence, 2-D tiling =================
// 128 CTAs: dir (2) x 4 batch-blocks x 16 col-blocks.
// CTA: M=16 batch rows, N=64 gate-interleaved cols (16 units x 4 gates), K'=768.
// 8 warps = 4 N-quarters (16 cols) x 2 K-halves (24 k-steps). Per-warp MMA work
// identical to R8 (24 A-ldsm + 48 mma); h staging is 16KB (was 64KB).
#define AS_STR 520          // 512 + 8 pad (bf16) — A is [hi(256)|lo(256)]
#define BS_STR 776          // 768 + 8 pad (bf16)
#define LSTM2_SMEM ((16 * AS_STR + 64 * BS_STR) * 2 + 3 * 16 * 64 * 4)

__global__ __launch_bounds__(256, 1)
void lstm_mma(const float* __restrict__ gatesF, const float* __restrict__ gatesB,
              const float* __restrict__ whhF, const float* __restrict__ whhB,
              float* __restrict__ hs_out)
{
    extern __shared__ char smraw[];
    __nv_bfloat16* As = (__nv_bfloat16*)smraw;                 // 16 x AS_STR
    __nv_bfloat16* Bs = As + 16 * AS_STR;                      // 64 x BS_STR
    float* gsm   = (float*)(Bs + 64 * BS_STR);                 // 16 x 64
    float* ssum0 = gsm + 16 * 64;
    float* ssum1 = ssum0 + 16 * 64;

    int bx = blockIdx.x;
    int dir  = bx >> 6;
    int bblk = (bx >> 4) & 3;       // batch block: rows b0..b0+15
    int cblk = bx & 15;             // col block: 16 hidden units
    int b0 = bblk * 16;
    int jbase = cblk * 16;
    int tid = threadIdx.x;
    int wid = tid >> 5, lane = tid & 31;

    const float* W     = dir ? whhB : whhF;
    const float* gates = dir ? gatesB : gatesF;

    // Build W slice: Bs[r][k], r = gate-interleaved col (u*4+g, 0..63),
    // k regions: [hi(256) | lo(256) | hi(256)]
    for (int i = tid; i < 64 * 768; i += 256) {
        int r = i / 768, k = i - r * 768;
        int j = jbase + (r >> 2);
        int g = r & 3;
        int korig = k & 255;
        float w = W[((long)(g * Hh + j)) * Hh + korig];
        __nv_bfloat16 hi = __float2bfloat16_rn(w);
        __nv_bfloat16 v;
        if (k >= 256 && k < 512) v = __float2bfloat16_rn(w - __bfloat162float(hi));
        else v = hi;
        Bs[r * BS_STR + k] = v;
    }
    __syncthreads();

    uint32_t aB = smem_u32(As);
    uint32_t bB = smem_u32(Bs);
    int wn = (wid & 3) * 16;       // N quarter: cols wn..wn+15
    int kh = wid >> 2;             // K half: 0 or 1
    float* sdst = kh ? ssum1 : ssum0;

    // Preload B fragments for my (N quarter, K half): 24 k-steps, loop-invariant.
    uint32_t breg[24][4];
#pragma unroll
    for (int si = 0; si < 24; si++) {
        int s = kh * 24 + si;
        int rowB = wn + (lane & 7) + ((lane >> 4) << 3);
        int colB = s * 16 + (((lane >> 3) & 1) << 3);
        ldsm_x4(breg[si][0], breg[si][1], breg[si][2], breg[si][3],
                bB + (rowB * BS_STR + colB) * 2);
    }

    // cell ownership: thread owns (b_local = tid>>4, u = tid&15); one c register
    int b_local = tid >> 4, u = tid & 15;
    int bglob = b0 + b_local;
    int j = jbase + u;
    {
        __nv_bfloat16 z = __float2bfloat16_rn(0.f);
        g_hsplit[0][dir][bglob * 512 + j] = z;
        g_hsplit[0][dir][bglob * 512 + 256 + j] = z;
    }
    float c = 0.f;
    grid_sync_dir(dir);

    for (int t = 0; t < Tt; t++) {
        const __nv_bfloat16* hin = g_hsplit[t & 1][dir];
        int tin = dir ? (Tt - 1 - t) : t;

        // stage h tile (16 rows x 512 bf16 = 64 int4 per row = 1024 int4)
        const int4* src = (const int4*)(hin + (long)b0 * 512);
#pragma unroll
        for (int i = 0; i < 4; i++) {
            int idx = tid + i * 256;           // 0..1023
            int row = idx >> 6, ch = idx & 63;
            int4 v = __ldcg(src + row * 64 + ch);
            *(int4*)(As + row * AS_STR + ch * 8) = v;
        }
        // stage input gates: 16 batch x 64 gi-cols = 256 float4 loads
        {
            int bl = tid >> 4;                 // batch row 0..15
            int g  = (tid >> 2) & 3;           // gate
            int q  = tid & 3;                  // unit group (4 units)
            float4 gv = __ldg((const float4*)(gates + ((long)(b0 + bl) * Tt + tin) * G4
                                              + g * Hh + jbase + q * 4));
            gsm[bl * 64 + (q * 4 + 0) * 4 + g] = gv.x;
            gsm[bl * 64 + (q * 4 + 1) * 4 + g] = gv.y;
            gsm[bl * 64 + (q * 4 + 2) * 4 + g] = gv.z;
            gsm[bl * 64 + (q * 4 + 3) * 4 + g] = gv.w;
        }
        __syncthreads();

        // MMA: warp computes 16 batch rows x 16 cols over its K half (24 k-steps)
        float acc0[4] = {0.f, 0.f, 0.f, 0.f};
        float acc1[4] = {0.f, 0.f, 0.f, 0.f};
#pragma unroll
        for (int si = 0; si < 24; si++) {
            int s = kh * 24 + si;
            int kc = (s < 32) ? (s & 15) * 16 : 256 + (s - 32) * 16;  // A col: [hi|hi|lo]
            uint32_t af[4];
            ldsm_x4(af[0], af[1], af[2], af[3],
                    aB + (((lane & 15)) * AS_STR + kc + (lane >> 4) * 8) * 2);
            uint32_t bf0[2] = {breg[si][0], breg[si][1]};
            uint32_t bf1[2] = {breg[si][2], breg[si][3]};
            mma16816(acc0, af, bf0);
            mma16816(acc1, af, bf1);
        }

        // write partial sums (16 x 64 layout)
        {
            int r = lane >> 2, cp = (lane & 3) * 2;
            int m1 = r, m2 = r + 8;
            *(float2*)&sdst[m1 * 64 + wn + cp]     = make_float2(acc0[0], acc0[1]);
            *(float2*)&sdst[m2 * 64 + wn + cp]     = make_float2(acc0[2], acc0[3]);
            *(float2*)&sdst[m1 * 64 + wn + 8 + cp] = make_float2(acc1[0], acc1[1]);
            *(float2*)&sdst[m2 * 64 + wn + 8 + cp] = make_float2(acc1[2], acc1[3]);
        }
        __syncthreads();

        // cell update: thread owns (b_local, u)
        int base = b_local * 64 + u * 4;
        float gi = gsm[base + 0] + ssum0[base + 0] + ssum1[base + 0];
        float gf = gsm[base + 1] + ssum0[base + 1] + ssum1[base + 1];
        float gg = gsm[base + 2] + ssum0[base + 2] + ssum1[base + 2];
        float go = gsm[base + 3] + ssum0[base + 3] + ssum1[base + 3];

        float ii = 1.f / (1.f + expf(-gi));
        float ff = 1.f / (1.f + expf(-gf));
        float tg = tanhf(gg);
        float oo = 1.f / (1.f + expf(-go));
        c = ff * c + ii * tg;
        float h = oo * tanhf(c);

        __nv_bfloat16 hi = __float2bfloat16_rn(h);
        __nv_bfloat16 lo = __float2bfloat16_rn(h - __bfloat162float(hi));
        __nv_bfloat16* hnext = g_hsplit[(t + 1) & 1][dir];
        hnext[bglob * 512 + j] = hi;
        hnext[bglob * 512 + 256 + j] = lo;
        hs_out[((long)bglob * Tt + tin) * TC + dir * Hh + j] = h;

        grid_sync_dir(dir);
    }
}

// ================= misc =================
__global__ void copy_right(const float* __restrict__ hs, float* __restrict__ cat) {
    long i = (long)blockIdx.x * blockDim.x + threadIdx.x;
    if (i < (long)ROWS * TC) {
        long m = i / TC, j = i % TC;
        cat[m * 1024 + 512 + j] = hs[i];
    }
}

__global__ void softmax_rows(const float* __restrict__ S, __nv_bfloat16* __restrict__ dst) {
    const float* row = S + (long)blockIdx.x * Tt;
    __nv_bfloat16* d = dst + (long)blockIdx.x * 1536;
    int tid = threadIdx.x;   // 128
    __shared__ float red[4];

    float mx = -1e30f;
    for (int j = tid; j < Tt; j += 128) mx = fmaxf(mx, row[j]);
#pragma unroll
    for (int o = 16; o; o >>= 1) mx = fmaxf(mx, __shfl_xor_sync(0xffffffffu, mx, o));
    if ((tid & 31) == 0) red[tid >> 5] = mx;
    __syncthreads();
    mx = fmaxf(fmaxf(red[0], red[1]), fmaxf(red[2], red[3]));

    float sum = 0.f;
    float e[4];
#pragma unroll
    for (int q = 0; q < 4; q++) {
        e[q] = expf(row[tid + q * 128] - mx);
        sum += e[q];
    }
#pragma unroll
    for (int o = 16; o; o >>= 1) sum += __shfl_xor_sync(0xffffffffu, sum, o);
    __syncthreads();
    if ((tid & 31) == 0) red[tid >> 5] = sum;
    __syncthreads();
    sum = red[0] + red[1] + red[2] + red[3];
    float inv = 1.f / sum;
#pragma unroll
    for (int q = 0; q < 4; q++) {
        int jj = tid + q * 128;
        float p = e[q] * inv;
        __nv_bfloat16 hi = __float2bfloat16_rn(p);
        __nv_bfloat16 lo = __float2bfloat16_rn(p - __bfloat162float(hi));
        d[jj] = hi; d[512 + jj] = hi; d[1024 + jj] = lo;
    }
}

__global__ void bn_stats(const float* __restrict__ Y, float* __restrict__ mean,
                         float* __restrict__ istd) {
    int ch = blockIdx.x;
    int tid = threadIdx.x;
    __shared__ float rs[8], rq[8];
    float s = 0.f, q = 0.f;
    for (int i = tid; i < Nn * Tt; i += 256) {
        int n = i >> 9, p = i & 511;
        float v = Y[(long)n * 25600 + ch * 512 + p];
        s += v; q += v * v;
    }
#pragma unroll
    for (int o = 16; o; o >>= 1) { s += __shfl_xor_sync(0xffffffffu, s, o); q += __shfl_xor_sync(0xffffffffu, q, o); }
    if ((tid & 31) == 0) { rs[tid >> 5] = s; rq[tid >> 5] = q; }
    __syncthreads();
    if (tid == 0) {
        s = 0.f; q = 0.f;
        for (int w = 0; w < 8; w++) { s += rs[w]; q += rq[w]; }
        float m = s / (float)(Nn * Tt);
        float var = q / (float)(Nn * Tt) - m * m;
        mean[ch] = m;
        istd[ch] = rsqrtf(var + 1e-5f);
    }
}

__global__ void bn_apply(float* __restrict__ Y, const float* __restrict__ mean,
                         const float* __restrict__ istd, const float* __restrict__ gam,
                         const float* __restrict__ bet) {
    long i = (long)blockIdx.x * blockDim.x + threadIdx.x;
    if (i < (long)ROWS * 50) {
        long r = i % 25600;
        int ch = (int)(r >> 9);
        Y[i] = (Y[i] - mean[ch]) * istd[ch] * gam[ch] + bet[ch];
    }
}

__global__ void gemm_bt64(const float* __restrict__ A, const float* __restrict__ B,
                          const float* __restrict__ bias, float* __restrict__ C,
                          int M, int N, int K, int ldc, int relu)
{
    __shared__ float As[16][64];
    __shared__ float Bs[16][64];
    int tx = threadIdx.x, ty = threadIdx.y;
    int tid = ty * 16 + tx;
    int m0 = blockIdx.y * 64, n0 = blockIdx.x * 64;

    float acc[4][4];
#pragma unroll
    for (int i = 0; i < 4; i++)
#pragma unroll
        for (int j = 0; j < 4; j++) acc[i][j] = 0.f;

    int lrow = tid >> 2;
    int lk   = (tid & 3) * 4;

    for (int k0 = 0; k0 < K; k0 += 16) {
        {
            float4 v = make_float4(0.f, 0.f, 0.f, 0.f);
            int m = m0 + lrow;
            if (m < M) v = *(const float4*)(A + (long)m * K + k0 + lk);
            As[lk + 0][lrow] = v.x; As[lk + 1][lrow] = v.y;
            As[lk + 2][lrow] = v.z; As[lk + 3][lrow] = v.w;
        }
        {
            float4 v = make_float4(0.f, 0.f, 0.f, 0.f);
            int n = n0 + lrow;
            if (n < N) v = *(const float4*)(B + (long)n * K + k0 + lk);
            Bs[lk + 0][lrow] = v.x; Bs[lk + 1][lrow] = v.y;
            Bs[lk + 2][lrow] = v.z; Bs[lk + 3][lrow] = v.w;
        }
        __syncthreads();
#pragma unroll
        for (int kk = 0; kk < 16; kk++) {
            float4 a = *(const float4*)&As[kk][ty * 4];
            float4 b = *(const float4*)&Bs[kk][tx * 4];
            acc[0][0] += a.x * b.x; acc[0][1] += a.x * b.y; acc[0][2] += a.x * b.z; acc[0][3] += a.x * b.w;
            acc[1][0] += a.y * b.x; acc[1][1] += a.y * b.y; acc[1][2] += a.y * b.z; acc[1][3] += a.y * b.w;
            acc[2][0] += a.z * b.x; acc[2][1] += a.z * b.y; acc[2][2] += a.z * b.z; acc[2][3] += a.z * b.w;
            acc[3][0] += a.w * b.x; acc[3][1] += a.w * b.y; acc[3][2] += a.w * b.z; acc[3][3] += a.w * b.w;
        }
        __syncthreads();
    }
#pragma unroll
    for (int i = 0; i < 4; i++) {
        int m = m0 + ty * 4 + i;
        if (m >= M) continue;
#pragma unroll
        for (int j = 0; j < 4; j++) {
            int n = n0 + tx * 4 + j;
            if (n >= N) continue;
            float v = acc[i][j];
            if (bias) v += bias[n];
            if (relu) v = fmaxf(v, 0.f);
            C[(long)m * ldc + n] = v;
        }
    }
}

template <int K, int N, bool RELU>
__global__ void small_fc(const float* __restrict__ X, const float* __restrict__ W,
                         const float* __restrict__ bias, float* __restrict__ Y) {
    __shared__ float xs[128 * K];
    __shared__ float ws[N * K];
    __shared__ float bs[N];
    int tid = threadIdx.x;
    long m0 = (long)blockIdx.x * 128;
    for (int i = tid; i < N * K; i += 128) ws[i] = W[i];
    for (int i = tid; i < N; i += 128) bs[i] = bias[i];
    for (int i = tid; i < 128 * K; i += 128) xs[i] = X[m0 * K + i];
    __syncthreads();
    long m = m0 + tid;
#pragma unroll
    for (int j = 0; j < N; j++) {
        float acc = bs[j];
#pragma unroll
        for (int k = 0; k < K; k++) acc += xs[tid * K + k] * ws[j * K + k];
        if (RELU) acc = fmaxf(acc, 0.f);
        Y[m * N + j] = acc;
    }
}

// ================= host orchestration =================
extern "C" void kernel_launch(void* const* d_in, const int* in_sizes, int n_in,
                              void* d_out, int out_size)
{
    const float* x     = (const float*)d_in[0];
    const float* wih0f = (const float*)d_in[1];
    const float* whh0f = (const float*)d_in[2];
    const float* b0f   = (const float*)d_in[3];
    const float* wih0b = (const float*)d_in[4];
    const float* whh0b = (const float*)d_in[5];
    const float* b0b   = (const float*)d_in[6];
    const float* wih1f = (const float*)d_in[7];
    const float* whh1f = (const float*)d_in[8];
    const float* b1f   = (const float*)d_in[9];
    const float* wih1b = (const float*)d_in[10];
    const float* whh1b = (const float*)d_in[11];
    const float* b1b   = (const float*)d_in[12];
    const float* fc1w  = (const float*)d_in[13];
    const float* fc1b  = (const float*)d_in[14];
    const float* bng   = (const float*)d_in[15];
    const float* bnb   = (const float*)d_in[16];
    const float* fc2w  = (const float*)d_in[17];
    const float* fc2b  = (const float*)d_in[18];
    const float* fc3w  = (const float*)d_in[19];
    const float* fc3b  = (const float*)d_in[20];
    const float* fc4w  = (const float*)d_in[21];
    const float* fc4b  = (const float*)d_in[22];
    float* out = (float*)d_out;

    float *gF, *gB, *hs0, *hs1, *sc, *cat, *f1, *f2, *f3, *mean, *istd;
    __nv_bfloat16 *xA, *w0fB, *w0bB, *w1fB, *w1bB, *hs0A, *hs1A, *hs1B, *hsTB, *attnA;
    cudaGetSymbolAddress((void**)&gF,   g_gatesF);
    cudaGetSymbolAddress((void**)&gB,   g_gatesB);
    cudaGetSymbolAddress((void**)&hs0,  g_hs0);
    cudaGetSymbolAddress((void**)&hs1,  g_hs1);
    cudaGetSymbolAddress((void**)&sc,   g_scores);
    cudaGetSymbolAddress((void**)&cat,  g_cat);
    cudaGetSymbolAddress((void**)&f1,   g_fc1);
    cudaGetSymbolAddress((void**)&f2,   g_fc2);
    cudaGetSymbolAddress((void**)&f3,   g_fc3);
    cudaGetSymbolAddress((void**)&mean, g_mean);
    cudaGetSymbolAddress((void**)&istd, g_istd);
    cudaGetSymbolAddress((void**)&xA,    g_xA);
    cudaGetSymbolAddress((void**)&w0fB,  g_w0fB);
    cudaGetSymbolAddress((void**)&w0bB,  g_w0bB);
    cudaGetSymbolAddress((void**)&w1fB,  g_w1fB);
    cudaGetSymbolAddress((void**)&w1bB,  g_w1bB);
    cudaGetSymbolAddress((void**)&hs0A,  g_hs0A);
    cudaGetSymbolAddress((void**)&hs1A,  g_hs1A);
    cudaGetSymbolAddress((void**)&hs1B,  g_hs1B);
    cudaGetSymbolAddress((void**)&hsTB,  g_hsTB);
    cudaGetSymbolAddress((void**)&attnA, g_attnA);

    cudaFuncSetAttribute(lstm_mma, cudaFuncAttributeMaxDynamicSharedMemorySize, LSTM2_SMEM);

    // ---- conversions ----
    conv_split<<<(int)(((long)ROWS * Dd + 255) / 256), 256>>>(x, xA, 7, (long)ROWS * Dd, 0);
    conv_split<<<(G4 * Dd + 255) / 256, 256>>>(wih0f, w0fB, 7, (long)G4 * Dd, 1);
    conv_split<<<(G4 * Dd + 255) / 256, 256>>>(wih0b, w0bB, 7, (long)G4 * Dd, 1);
    conv_split<<<(G4 * TC + 255) / 256, 256>>>(wih1f, w1fB, 9, (long)G4 * TC, 1);
    conv_split<<<(G4 * TC + 255) / 256, 256>>>(wih1b, w1bB, 9, (long)G4 * TC, 1);

    // ---- layer 0 ----
    gemm_mma<<<dim3(8, 256), 256>>>(xA, w0fB, b0f, gF, 384, G4, 0, 0, 0);
    gemm_mma<<<dim3(8, 256), 256>>>(xA, w0bB, b0b, gB, 384, G4, 0, 0, 0);
    lstm_mma<<<128, 256, LSTM2_SMEM>>>(gF, gB, whh0f, whh0b, hs0);

    // ---- layer 1 ----
    conv_split<<<(int)(((long)ROWS * TC + 255) / 256), 256>>>(hs0, hs0A, 9, (long)ROWS * TC, 0);
    gemm_mma<<<dim3(8, 256), 256>>>(hs0A, w1fB, b1f, gF, 1536, G4, 0, 0, 0);
    gemm_mma<<<dim3(8, 256), 256>>>(hs0A, w1bB, b1b, gB, 1536, G4, 0, 0, 0);
    lstm_mma<<<128, 256, LSTM2_SMEM>>>(gF, gB, whh1f, whh1b, hs1);

    // ---- attention ----
    conv_split<<<(int)(((long)ROWS * TC + 255) / 256), 256>>>(hs1, hs1A, 9, (long)ROWS * TC, 0);
    conv_split<<<(int)(((long)ROWS * TC + 255) / 256), 256>>>(hs1, hs1B, 9, (long)ROWS * TC, 1);
    transp_convB<<<dim3(16, 16, Nn), dim3(32, 32)>>>(hs1, hsTB);

    long sAB = (long)Tt * 1536;
    gemm_mma<<<dim3(4, 4, Nn), 256>>>(hs1A, hs1B, nullptr, sc, 1536, Tt,
                                      sAB, sAB, (long)Tt * Tt);
    softmax_rows<<<Nn * Tt, 128>>>(sc, attnA);
    gemm_mma<<<dim3(4, 4, Nn), 256>>>(attnA, hsTB, nullptr, cat, 1536, 1024,
                                      sAB, sAB, (long)Tt * 1024);
    copy_right<<<(int)(((long)ROWS * TC + 255) / 256), 256>>>(hs1, cat);

    // ---- head ----
    gemm_bt64<<<dim3(1, 512), dim3(16, 16)>>>(cat, fc1w, fc1b, f1, ROWS, 50, 1024, 50, 1);
    bn_stats<<<50, 256>>>(f1, mean, istd);
    bn_apply<<<(int)(((long)ROWS * 50 + 255) / 256), 256>>>(f1, mean, istd, bng, bnb);
    small_fc<50, 25, true ><<<ROWS / 128, 128>>>(f1, fc2w, fc2b, f2);
    small_fc<25, 10, true ><<<ROWS / 128, 128>>>(f2, fc3w, fc3b, f3);
    small_fc<10, 2,  false><<<ROWS / 128, 128>>>(f3, fc4w, fc4b, out);
}

// round 13
// speedup vs baseline: 1.1627x; 1.0033x over previous
#include <cuda_runtime.h>
#include <cuda_bf16.h>
#include <math.h>
#include <cstdint>

#define Nn 64
#define Tt 512
#define Dd 128
#define Hh 256
#define G4 1024
#define TC 512
#define ROWS (Nn*Tt)

// ================= static scratch =================
__device__ float g_gatesF[(size_t)ROWS * G4];
__device__ float g_gatesB[(size_t)ROWS * G4];
__device__ float g_hs0[(size_t)ROWS * TC];
__device__ float g_hs1[(size_t)ROWS * TC];
__device__ float g_scores[(size_t)Nn * Tt * Tt];
__device__ float g_cat[(size_t)ROWS * 1024];
__device__ float g_fc1[(size_t)ROWS * 50];
__device__ float g_fc2[(size_t)ROWS * 25];
__device__ float g_fc3[(size_t)ROWS * 10];
__device__ float g_mean[64];
__device__ float g_istd[64];
__device__ unsigned g_bcnt[8][64];            // per (dir,bblk) barrier, 256B apart
__device__ volatile unsigned g_bgen[8][64];

// h state as split bf16 [hi(256)|lo(256)] per batch row; double buffered, per dir
__device__ __align__(16) __nv_bfloat16 g_hsplit[2][2][Nn * 512];

// bf16 split buffers (K' = 3K)
__device__ __align__(16) __nv_bfloat16 g_xA[(size_t)ROWS * 384];
__device__ __align__(16) __nv_bfloat16 g_w0fB[(size_t)G4 * 384];
__device__ __align__(16) __nv_bfloat16 g_w0bB[(size_t)G4 * 384];
__device__ __align__(16) __nv_bfloat16 g_w1fB[(size_t)G4 * 1536];
__device__ __align__(16) __nv_bfloat16 g_w1bB[(size_t)G4 * 1536];
__device__ __align__(16) __nv_bfloat16 g_hs0A[(size_t)ROWS * 1536];
__device__ __align__(16) __nv_bfloat16 g_hs1A[(size_t)ROWS * 1536];
__device__ __align__(16) __nv_bfloat16 g_hs1B[(size_t)ROWS * 1536];
__device__ __align__(16) __nv_bfloat16 g_hsTB[(size_t)ROWS * 1536];
__device__ __align__(16) __nv_bfloat16 g_attnA[(size_t)ROWS * 1536];

// ================= per-(dir,bblk) grid barrier (16 CTAs each) =================
__device__ __forceinline__ void grid_sync_grp(int grp) {
    __syncthreads();
    if (threadIdx.x == 0) {
        __threadfence();
        unsigned gen = g_bgen[grp][0];
        if (atomicAdd(&g_bcnt[grp][0], 1) == 15) {
            g_bcnt[grp][0] = 0;
            __threadfence();
            g_bgen[grp][0] = gen + 1;
        } else {
            while (g_bgen[grp][0] == gen) { }
        }
    }
    __syncthreads();
}

// ================= HMMA helpers =================
__device__ __forceinline__ uint32_t smem_u32(const void* p) {
    uint32_t a;
    asm("{ .reg .u64 t; cvta.to.shared.u64 t, %1; cvt.u32.u64 %0, t; }" : "=r"(a) : "l"(p));
    return a;
}
__device__ __forceinline__ void ldsm_x4(uint32_t& r0, uint32_t& r1, uint32_t& r2, uint32_t& r3,
                                        uint32_t addr) {
    asm volatile("ldmatrix.sync.aligned.m8n8.x4.shared.b16 {%0,%1,%2,%3}, [%4];"
                 : "=r"(r0), "=r"(r1), "=r"(r2), "=r"(r3) : "r"(addr));
}
__device__ __forceinline__ void ldsm_x2(uint32_t& r0, uint32_t& r1, uint32_t addr) {
    asm volatile("ldmatrix.sync.aligned.m8n8.x2.shared.b16 {%0,%1}, [%2];"
                 : "=r"(r0), "=r"(r1) : "r"(addr));
}
__device__ __forceinline__ void mma16816(float* c, const uint32_t* a, const uint32_t* b) {
    asm volatile(
        "mma.sync.aligned.m16n8k16.row.col.f32.bf16.bf16.f32 "
        "{%0,%1,%2,%3}, {%4,%5,%6,%7}, {%8,%9}, {%0,%1,%2,%3};"
        : "+f"(c[0]), "+f"(c[1]), "+f"(c[2]), "+f"(c[3])
        : "r"(a[0]), "r"(a[1]), "r"(a[2]), "r"(a[3]), "r"(b[0]), "r"(b[1]));
}

// ================= HMMA bf16 GEMM: C(MxN) = A(MxK')·B(NxK')^T =================
#define SMSTRIDE 72

__global__ __launch_bounds__(256)
void gemm_mma(const __nv_bfloat16* __restrict__ Ag, const __nv_bfloat16* __restrict__ Bg,
              const float* __restrict__ bias, float* __restrict__ Cg,
              int Kp, int ldc, long sA, long sB, long sC)
{
    __shared__ __nv_bfloat16 As[128 * SMSTRIDE];
    __shared__ __nv_bfloat16 Bs[128 * SMSTRIDE];

    int tid = threadIdx.x;
    int wid = tid >> 5, lane = tid & 31;
    int warp_m = wid & 1;
    int warp_n = wid >> 1;

    const __nv_bfloat16* A = Ag + (long)blockIdx.z * sA + (long)blockIdx.y * 128 * Kp;
    const __nv_bfloat16* B = Bg + (long)blockIdx.z * sB + (long)blockIdx.x * 128 * Kp;
    float* C = Cg + (long)blockIdx.z * sC;

    uint32_t aBase = smem_u32(As);
    uint32_t bBase = smem_u32(Bs);

    float acc[4][4][4];
#pragma unroll
    for (int mi = 0; mi < 4; mi++)
#pragma unroll
        for (int ni = 0; ni < 4; ni++)
#pragma unroll
            for (int q = 0; q < 4; q++) acc[mi][ni][q] = 0.f;

    int NC = Kp >> 6;
    for (int c = 0; c < NC; c++) {
#pragma unroll
        for (int p = 0; p < 4; p++) {
            int idx = tid + p * 256;
            int row = idx >> 3, cg = (idx & 7) * 8;
            int4 va = *(const int4*)(A + (long)row * Kp + c * 64 + cg);
            *(int4*)(As + row * SMSTRIDE + cg) = va;
            int4 vb = *(const int4*)(B + (long)row * Kp + c * 64 + cg);
            *(int4*)(Bs + row * SMSTRIDE + cg) = vb;
        }
        __syncthreads();

#pragma unroll
        for (int kk = 0; kk < 4; kk++) {
            int k0 = kk * 16;
            uint32_t af[4][4], bfr[4][2];
#pragma unroll
            for (int mi = 0; mi < 4; mi++) {
                int row = warp_m * 64 + mi * 16 + (lane & 15);
                int col = k0 + (lane >> 4) * 8;
                ldsm_x4(af[mi][0], af[mi][1], af[mi][2], af[mi][3],
                        aBase + (row * SMSTRIDE + col) * 2);
            }
#pragma unroll
            for (int ni = 0; ni < 4; ni++) {
                int row = warp_n * 32 + ni * 8 + (lane & 7);
                int col = k0 + ((lane >> 3) & 1) * 8;
                ldsm_x2(bfr[ni][0], bfr[ni][1], bBase + (row * SMSTRIDE + col) * 2);
            }
#pragma unroll
            for (int mi = 0; mi < 4; mi++)
#pragma unroll
                for (int ni = 0; ni < 4; ni++)
                    mma16816(acc[mi][ni], af[mi], bfr[ni]);
        }
        __syncthreads();
    }

    int m_base = blockIdx.y * 128 + warp_m * 64;
    int n_base = blockIdx.x * 128 + warp_n * 32;
    int r = lane >> 2, cp = (lane & 3) * 2;
#pragma unroll
    for (int mi = 0; mi < 4; mi++) {
#pragma unroll
        for (int ni = 0; ni < 4; ni++) {
            int m = m_base + mi * 16 + r;
            int n = n_base + ni * 8 + cp;
            float2 v0 = make_float2(acc[mi][ni][0], acc[mi][ni][1]);
            float2 v1 = make_float2(acc[mi][ni][2], acc[mi][ni][3]);
            if (bias) {
                float b0 = bias[n], b1 = bias[n + 1];
                v0.x += b0; v0.y += b1;
                v1.x += b0; v1.y += b1;
            }
            *(float2*)(C + (long)m * ldc + n) = v0;
            *(float2*)(C + (long)(m + 8) * ldc + n) = v1;
        }
    }
}

// ================= split-bf16 conversion =================
__global__ void conv_split(const float* __restrict__ src, __nv_bfloat16* __restrict__ dst,
                           int kshift, long total, int flavB)
{
    long i = (long)blockIdx.x * blockDim.x + threadIdx.x;
    if (i >= total) return;
    int K = 1 << kshift;
    long m = i >> kshift;
    int k = (int)(i & (K - 1));
    float x = src[i];
    __nv_bfloat16 hi = __float2bfloat16_rn(x);
    __nv_bfloat16 lo = __float2bfloat16_rn(x - __bfloat162float(hi));
    __nv_bfloat16* d = dst + m * 3 * K;
    d[k] = hi;
    if (flavB) { d[K + k] = lo; d[2 * K + k] = hi; }
    else       { d[K + k] = hi; d[2 * K + k] = lo; }
}

__global__ void transp_convB(const float* __restrict__ hs, __nv_bfloat16* __restrict__ dst)
{
    __shared__ float tile[32][33];
    int n = blockIdx.z;
    int s0 = blockIdx.y * 32, h0 = blockIdx.x * 32;
    int tx = threadIdx.x, ty = threadIdx.y;
    tile[ty][tx] = hs[((long)n * Tt + s0 + ty) * TC + h0 + tx];
    __syncthreads();
    float x = tile[tx][ty];
    __nv_bfloat16 hi = __float2bfloat16_rn(x);
    __nv_bfloat16 lo = __float2bfloat16_rn(x - __bfloat162float(hi));
    __nv_bfloat16* d = dst + (long)n * Tt * 1536 + (long)(h0 + ty) * 1536;
    int s = s0 + tx;
    d[s] = hi; d[512 + s] = lo; d[1024 + s] = hi;
}

// ================= persistent LSTM with HMMA recurrence, 2-D tiling =================
// 128 CTAs: dir (2) x 4 batch-blocks x 16 col-blocks. CTA: M=16 batch rows,
// N=64 gate-interleaved cols, K'=768. 8 warps = 4 N-quarters x 2 K-halves.
// Barrier groups: (dir, bblk) = 16 CTAs — batch blocks are independent.
#define AS_STR 520
#define BS_STR 776
#define LSTM2_SMEM ((16 * AS_STR + 64 * BS_STR) * 2 + 3 * 16 * 64 * 4)

__global__ __launch_bounds__(256, 1)
void lstm_mma(const float* __restrict__ gatesF, const float* __restrict__ gatesB,
              const float* __restrict__ whhF, const float* __restrict__ whhB,
              float* __restrict__ hs_out)
{
    extern __shared__ char smraw[];
    __nv_bfloat16* As = (__nv_bfloat16*)smraw;
    __nv_bfloat16* Bs = As + 16 * AS_STR;
    float* gsm   = (float*)(Bs + 64 * BS_STR);
    float* ssum0 = gsm + 16 * 64;
    float* ssum1 = ssum0 + 16 * 64;

    int bx = blockIdx.x;
    int dir  = bx >> 6;
    int bblk = (bx >> 4) & 3;
    int cblk = bx & 15;
    int grp = dir * 4 + bblk;
    int b0 = bblk * 16;
    int jbase = cblk * 16;
    int tid = threadIdx.x;
    int wid = tid >> 5, lane = tid & 31;

    const float* W     = dir ? whhB : whhF;
    const float* gates = dir ? gatesB : gatesF;

    // Build W slice: Bs[r][k], r = gate-interleaved col (u*4+g, 0..63),
    // k regions: [hi(256) | lo(256) | hi(256)]
    for (int i = tid; i < 64 * 768; i += 256) {
        int r = i / 768, k = i - r * 768;
        int j = jbase + (r >> 2);
        int g = r & 3;
        int korig = k & 255;
        float w = W[((long)(g * Hh + j)) * Hh + korig];
        __nv_bfloat16 hi = __float2bfloat16_rn(w);
        __nv_bfloat16 v;
        if (k >= 256 && k < 512) v = __float2bfloat16_rn(w - __bfloat162float(hi));
        else v = hi;
        Bs[r * BS_STR + k] = v;
    }
    __syncthreads();

    uint32_t aB = smem_u32(As);
    uint32_t bB = smem_u32(Bs);
    int wn = (wid & 3) * 16;
    int kh = wid >> 2;
    float* sdst = kh ? ssum1 : ssum0;

    uint32_t breg[24][4];
#pragma unroll
    for (int si = 0; si < 24; si++) {
        int s = kh * 24 + si;
        int rowB = wn + (lane & 7) + ((lane >> 4) << 3);
        int colB = s * 16 + (((lane >> 3) & 1) << 3);
        ldsm_x4(breg[si][0], breg[si][1], breg[si][2], breg[si][3],
                bB + (rowB * BS_STR + colB) * 2);
    }

    int b_local = tid >> 4, u = tid & 15;
    int bglob = b0 + b_local;
    int j = jbase + u;
    {
        __nv_bfloat16 z = __float2bfloat16_rn(0.f);
        g_hsplit[0][dir][bglob * 512 + j] = z;
        g_hsplit[0][dir][bglob * 512 + 256 + j] = z;
    }
    float c = 0.f;
    grid_sync_grp(grp);

    for (int t = 0; t < Tt; t++) {
        const __nv_bfloat16* hin = g_hsplit[t & 1][dir];
        int tin = dir ? (Tt - 1 - t) : t;

        const int4* src = (const int4*)(hin + (long)b0 * 512);
#pragma unroll
        for (int i = 0; i < 4; i++) {
            int idx = tid + i * 256;
            int row = idx >> 6, ch = idx & 63;
            int4 v = __ldcg(src + row * 64 + ch);
            *(int4*)(As + row * AS_STR + ch * 8) = v;
        }
        {
            int bl = tid >> 4;
            int g  = (tid >> 2) & 3;
            int q  = tid & 3;
            float4 gv = __ldg((const float4*)(gates + ((long)(b0 + bl) * Tt + tin) * G4
                                              + g * Hh + jbase + q * 4));
            gsm[bl * 64 + (q * 4 + 0) * 4 + g] = gv.x;
            gsm[bl * 64 + (q * 4 + 1) * 4 + g] = gv.y;
            gsm[bl * 64 + (q * 4 + 2) * 4 + g] = gv.z;
            gsm[bl * 64 + (q * 4 + 3) * 4 + g] = gv.w;
        }
        __syncthreads();

        float acc0[4] = {0.f, 0.f, 0.f, 0.f};
        float acc1[4] = {0.f, 0.f, 0.f, 0.f};
#pragma unroll
        for (int si = 0; si < 24; si++) {
            int s = kh * 24 + si;
            int kc = (s < 32) ? (s & 15) * 16 : 256 + (s - 32) * 16;
            uint32_t af[4];
            ldsm_x4(af[0], af[1], af[2], af[3],
                    aB + (((lane & 15)) * AS_STR + kc + (lane >> 4) * 8) * 2);
            uint32_t bf0[2] = {breg[si][0], breg[si][1]};
            uint32_t bf1[2] = {breg[si][2], breg[si][3]};
            mma16816(acc0, af, bf0);
            mma16816(acc1, af, bf1);
        }

        {
            int r = lane >> 2, cp = (lane & 3) * 2;
            int m1 = r, m2 = r + 8;
            *(float2*)&sdst[m1 * 64 + wn + cp]     = make_float2(acc0[0], acc0[1]);
            *(float2*)&sdst[m2 * 64 + wn + cp]     = make_float2(acc0[2], acc0[3]);
            *(float2*)&sdst[m1 * 64 + wn + 8 + cp] = make_float2(acc1[0], acc1[1]);
            *(float2*)&sdst[m2 * 64 + wn + 8 + cp] = make_float2(acc1[2], acc1[3]);
        }
        __syncthreads();

        int base = b_local * 64 + u * 4;
        float gi = gsm[base + 0] + ssum0[base + 0] + ssum1[base + 0];
        float gf = gsm[base + 1] + ssum0[base + 1] + ssum1[base + 1];
        float gg = gsm[base + 2] + ssum0[base + 2] + ssum1[base + 2];
        float go = gsm[base + 3] + ssum0[base + 3] + ssum1[base + 3];

        float ii = 1.f / (1.f + expf(-gi));
        float ff = 1.f / (1.f + expf(-gf));
        float tg = tanhf(gg);
        float oo = 1.f / (1.f + expf(-go));
        c = ff * c + ii * tg;
        float h = oo * tanhf(c);

        __nv_bfloat16 hi = __float2bfloat16_rn(h);
        __nv_bfloat16 lo = __float2bfloat16_rn(h - __bfloat162float(hi));
        __nv_bfloat16* hnext = g_hsplit[(t + 1) & 1][dir];
        hnext[bglob * 512 + j] = hi;
        hnext[bglob * 512 + 256 + j] = lo;
        hs_out[((long)bglob * Tt + tin) * TC + dir * Hh + j] = h;

        grid_sync_grp(grp);
    }
}

// ================= misc =================
__global__ void copy_right(const float* __restrict__ hs, float* __restrict__ cat) {
    long i = (long)blockIdx.x * blockDim.x + threadIdx.x;
    if (i < (long)ROWS * TC) {
        long m = i / TC, j = i % TC;
        cat[m * 1024 + 512 + j] = hs[i];
    }
}

__global__ void softmax_rows(const float* __restrict__ S, __nv_bfloat16* __restrict__ dst) {
    const float* row = S + (long)blockIdx.x * Tt;
    __nv_bfloat16* d = dst + (long)blockIdx.x * 1536;
    int tid = threadIdx.x;   // 128
    __shared__ float red[4];

    float mx = -1e30f;
    for (int j = tid; j < Tt; j += 128) mx = fmaxf(mx, row[j]);
#pragma unroll
    for (int o = 16; o; o >>= 1) mx = fmaxf(mx, __shfl_xor_sync(0xffffffffu, mx, o));
    if ((tid & 31) == 0) red[tid >> 5] = mx;
    __syncthreads();
    mx = fmaxf(fmaxf(red[0], red[1]), fmaxf(red[2], red[3]));

    float sum = 0.f;
    float e[4];
#pragma unroll
    for (int q = 0; q < 4; q++) {
        e[q] = expf(row[tid + q * 128] - mx);
        sum += e[q];
    }
#pragma unroll
    for (int o = 16; o; o >>= 1) sum += __shfl_xor_sync(0xffffffffu, sum, o);
    __syncthreads();
    if ((tid & 31) == 0) red[tid >> 5] = sum;
    __syncthreads();
    sum = red[0] + red[1] + red[2] + red[3];
    float inv = 1.f / sum;
#pragma unroll
    for (int q = 0; q < 4; q++) {
        int jj = tid + q * 128;
        float p = e[q] * inv;
        __nv_bfloat16 hi = __float2bfloat16_rn(p);
        __nv_bfloat16 lo = __float2bfloat16_rn(p - __bfloat162float(hi));
        d[jj] = hi; d[512 + jj] = hi; d[1024 + jj] = lo;
    }
}

__global__ void bn_stats(const float* __restrict__ Y, float* __restrict__ mean,
                         float* __restrict__ istd) {
    int ch = blockIdx.x;
    int tid = threadIdx.x;
    __shared__ float rs[8], rq[8];
    float s = 0.f, q = 0.f;
    for (int i = tid; i < Nn * Tt; i += 256) {
        int n = i >> 9, p = i & 511;
        float v = Y[(long)n * 25600 + ch * 512 + p];
        s += v; q += v * v;
    }
#pragma unroll
    for (int o = 16; o; o >>= 1) { s += __shfl_xor_sync(0xffffffffu, s, o); q += __shfl_xor_sync(0xffffffffu, q, o); }
    if ((tid & 31) == 0) { rs[tid >> 5] = s; rq[tid >> 5] = q; }
    __syncthreads();
    if (tid == 0) {
        s = 0.f; q = 0.f;
        for (int w = 0; w < 8; w++) { s += rs[w]; q += rq[w]; }
        float m = s / (float)(Nn * Tt);
        float var = q / (float)(Nn * Tt) - m * m;
        mean[ch] = m;
        istd[ch] = rsqrtf(var + 1e-5f);
    }
}

__global__ void bn_apply(float* __restrict__ Y, const float* __restrict__ mean,
                         const float* __restrict__ istd, const float* __restrict__ gam,
                         const float* __restrict__ bet) {
    long i = (long)blockIdx.x * blockDim.x + threadIdx.x;
    if (i < (long)ROWS * 50) {
        long r = i % 25600;
        int ch = (int)(r >> 9);
        Y[i] = (Y[i] - mean[ch]) * istd[ch] * gam[ch] + bet[ch];
    }
}

__global__ void gemm_bt64(const float* __restrict__ A, const float* __restrict__ B,
                          const float* __restrict__ bias, float* __restrict__ C,
                          int M, int N, int K, int ldc, int relu)
{
    __shared__ float As[16][64];
    __shared__ float Bs[16][64];
    int tx = threadIdx.x, ty = threadIdx.y;
    int tid = ty * 16 + tx;
    int m0 = blockIdx.y * 64, n0 = blockIdx.x * 64;

    float acc[4][4];
#pragma unroll
    for (int i = 0; i < 4; i++)
#pragma unroll
        for (int j = 0; j < 4; j++) acc[i][j] = 0.f;

    int lrow = tid >> 2;
    int lk   = (tid & 3) * 4;

    for (int k0 = 0; k0 < K; k0 += 16) {
        {
            float4 v = make_float4(0.f, 0.f, 0.f, 0.f);
            int m = m0 + lrow;
            if (m < M) v = *(const float4*)(A + (long)m * K + k0 + lk);
            As[lk + 0][lrow] = v.x; As[lk + 1][lrow] = v.y;
            As[lk + 2][lrow] = v.z; As[lk + 3][lrow] = v.w;
        }
        {
            float4 v = make_float4(0.f, 0.f, 0.f, 0.f);
            int n = n0 + lrow;
            if (n < N) v = *(const float4*)(B + (long)n * K + k0 + lk);
            Bs[lk + 0][lrow] = v.x; Bs[lk + 1][lrow] = v.y;
            Bs[lk + 2][lrow] = v.z; Bs[lk + 3][lrow] = v.w;
        }
        __syncthreads();
#pragma unroll
        for (int kk = 0; kk < 16; kk++) {
            float4 a = *(const float4*)&As[kk][ty * 4];
            float4 b = *(const float4*)&Bs[kk][tx * 4];
            acc[0][0] += a.x * b.x; acc[0][1] += a.x * b.y; acc[0][2] += a.x * b.z; acc[0][3] += a.x * b.w;
            acc[1][0] += a.y * b.x; acc[1][1] += a.y * b.y; acc[1][2] += a.y * b.z; acc[1][3] += a.y * b.w;
            acc[2][0] += a.z * b.x; acc[2][1] += a.z * b.y; acc[2][2] += a.z * b.z; acc[2][3] += a.z * b.w;
            acc[3][0] += a.w * b.x; acc[3][1] += a.w * b.y; acc[3][2] += a.w * b.z; acc[3][3] += a.w * b.w;
        }
        __syncthreads();
    }
#pragma unroll
    for (int i = 0; i < 4; i++) {
        int m = m0 + ty * 4 + i;
        if (m >= M) continue;
#pragma unroll
        for (int j = 0; j < 4; j++) {
            int n = n0 + tx * 4 + j;
            if (n >= N) continue;
            float v = acc[i][j];
            if (bias) v += bias[n];
            if (relu) v = fmaxf(v, 0.f);
            C[(long)m * ldc + n] = v;
        }
    }
}

template <int K, int N, bool RELU>
__global__ void small_fc(const float* __restrict__ X, const float* __restrict__ W,
                         const float* __restrict__ bias, float* __restrict__ Y) {
    __shared__ float xs[128 * K];
    __shared__ float ws[N * K];
    __shared__ float bs[N];
    int tid = threadIdx.x;
    long m0 = (long)blockIdx.x * 128;
    for (int i = tid; i < N * K; i += 128) ws[i] = W[i];
    for (int i = tid; i < N; i += 128) bs[i] = bias[i];
    for (int i = tid; i < 128 * K; i += 128) xs[i] = X[m0 * K + i];
    __syncthreads();
    long m = m0 + tid;
#pragma unroll
    for (int j = 0; j < N; j++) {
        float acc = bs[j];
#pragma unroll
        for (int k = 0; k < K; k++) acc += xs[tid * K + k] * ws[j * K + k];
        if (RELU) acc = fmaxf(acc, 0.f);
        Y[m * N + j] = acc;
    }
}

// ================= host orchestration =================
extern "C" void kernel_launch(void* const* d_in, const int* in_sizes, int n_in,
                              void* d_out, int out_size)
{
    const float* x     = (const float*)d_in[0];
    const float* wih0f = (const float*)d_in[1];
    const float* whh0f = (const float*)d_in[2];
    const float* b0f   = (const float*)d_in[3];
    const float* wih0b = (const float*)d_in[4];
    const float* whh0b = (const float*)d_in[5];
    const float* b0b   = (const float*)d_in[6];
    const float* wih1f = (const float*)d_in[7];
    const float* whh1f = (const float*)d_in[8];
    const float* b1f   = (const float*)d_in[9];
    const float* wih1b = (const float*)d_in[10];
    const float* whh1b = (const float*)d_in[11];
    const float* b1b   = (const float*)d_in[12];
    const float* fc1w  = (const float*)d_in[13];
    const float* fc1b  = (const float*)d_in[14];
    const float* bng   = (const float*)d_in[15];
    const float* bnb   = (const float*)d_in[16];
    const float* fc2w  = (const float*)d_in[17];
    const float* fc2b  = (const float*)d_in[18];
    const float* fc3w  = (const float*)d_in[19];
    const float* fc3b  = (const float*)d_in[20];
    const float* fc4w  = (const float*)d_in[21];
    const float* fc4b  = (const float*)d_in[22];
    float* out = (float*)d_out;

    float *gF, *gB, *hs0, *hs1, *sc, *cat, *f1, *f2, *f3, *mean, *istd;
    __nv_bfloat16 *xA, *w0fB, *w0bB, *w1fB, *w1bB, *hs0A, *hs1A, *hs1B, *hsTB, *attnA;
    cudaGetSymbolAddress((void**)&gF,   g_gatesF);
    cudaGetSymbolAddress((void**)&gB,   g_gatesB);
    cudaGetSymbolAddress((void**)&hs0,  g_hs0);
    cudaGetSymbolAddress((void**)&hs1,  g_hs1);
    cudaGetSymbolAddress((void**)&sc,   g_scores);
    cudaGetSymbolAddress((void**)&cat,  g_cat);
    cudaGetSymbolAddress((void**)&f1,   g_fc1);
    cudaGetSymbolAddress((void**)&f2,   g_fc2);
    cudaGetSymbolAddress((void**)&f3,   g_fc3);
    cudaGetSymbolAddress((void**)&mean, g_mean);
    cudaGetSymbolAddress((void**)&istd, g_istd);
    cudaGetSymbolAddress((void**)&xA,    g_xA);
    cudaGetSymbolAddress((void**)&w0fB,  g_w0fB);
    cudaGetSymbolAddress((void**)&w0bB,  g_w0bB);
    cudaGetSymbolAddress((void**)&w1fB,  g_w1fB);
    cudaGetSymbolAddress((void**)&w1bB,  g_w1bB);
    cudaGetSymbolAddress((void**)&hs0A,  g_hs0A);
    cudaGetSymbolAddress((void**)&hs1A,  g_hs1A);
    cudaGetSymbolAddress((void**)&hs1B,  g_hs1B);
    cudaGetSymbolAddress((void**)&hsTB,  g_hsTB);
    cudaGetSymbolAddress((void**)&attnA, g_attnA);

    cudaFuncSetAttribute(lstm_mma, cudaFuncAttributeMaxDynamicSharedMemorySize, LSTM2_SMEM);

    // ---- conversions ----
    conv_split<<<(int)(((long)ROWS * Dd + 255) / 256), 256>>>(x, xA, 7, (long)ROWS * Dd, 0);
    conv_split<<<(G4 * Dd + 255) / 256, 256>>>(wih0f, w0fB, 7, (long)G4 * Dd, 1);
    conv_split<<<(G4 * Dd + 255) / 256, 256>>>(wih0b, w0bB, 7, (long)G4 * Dd, 1);
    conv_split<<<(G4 * TC + 255) / 256, 256>>>(wih1f, w1fB, 9, (long)G4 * TC, 1);
    conv_split<<<(G4 * TC + 255) / 256, 256>>>(wih1b, w1bB, 9, (long)G4 * TC, 1);

    // ---- layer 0 ----
    gemm_mma<<<dim3(8, 256), 256>>>(xA, w0fB, b0f, gF, 384, G4, 0, 0, 0);
    gemm_mma<<<dim3(8, 256), 256>>>(xA, w0bB, b0b, gB, 384, G4, 0, 0, 0);
    lstm_mma<<<128, 256, LSTM2_SMEM>>>(gF, gB, whh0f, whh0b, hs0);

    // ---- layer 1 ----
    conv_split<<<(int)(((long)ROWS * TC + 255) / 256), 256>>>(hs0, hs0A, 9, (long)ROWS * TC, 0);
    gemm_mma<<<dim3(8, 256), 256>>>(hs0A, w1fB, b1f, gF, 1536, G4, 0, 0, 0);
    gemm_mma<<<dim3(8, 256), 256>>>(hs0A, w1bB, b1b, gB, 1536, G4, 0, 0, 0);
    lstm_mma<<<128, 256, LSTM2_SMEM>>>(gF, gB, whh1f, whh1b, hs1);

    // ---- attention ----
    conv_split<<<(int)(((long)ROWS * TC + 255) / 256), 256>>>(hs1, hs1A, 9, (long)ROWS * TC, 0);
    conv_split<<<(int)(((long)ROWS * TC + 255) / 256), 256>>>(hs1, hs1B, 9, (long)ROWS * TC, 1);
    transp_convB<<<dim3(16, 16, Nn), dim3(32, 32)>>>(hs1, hsTB);

    long sAB = (long)Tt * 1536;
    gemm_mma<<<dim3(4, 4, Nn), 256>>>(hs1A, hs1B, nullptr, sc, 1536, Tt,
                                      sAB, sAB, (long)Tt * Tt);
    softmax_rows<<<Nn * Tt, 128>>>(sc, attnA);
    gemm_mma<<<dim3(4, 4, Nn), 256>>>(attnA, hsTB, nullptr, cat, 1536, 1024,
                                      sAB, sAB, (long)Tt * 1024);
    copy_right<<<(int)(((long)ROWS * TC + 255) / 256), 256>>>(hs1, cat);

    // ---- head ----
    gemm_bt64<<<dim3(1, 512), dim3(16, 16)>>>(cat, fc1w, fc1b, f1, ROWS, 50, 1024, 50, 1);
    bn_stats<<<50, 256>>>(f1, mean, istd);
    bn_apply<<<(int)(((long)ROWS * 50 + 255) / 256), 256>>>(f1, mean, istd, bng, bnb);
    small_fc<50, 25, true ><<<ROWS / 128, 128>>>(f1, fc2w, fc2b, f2);
    small_fc<25, 10, true ><<<ROWS / 128, 128>>>(f2, fc3w, fc3b, f3);
    small_fc<10, 2,  false><<<ROWS / 128, 128>>>(f3, fc4w, fc4b, out);
}

// round 14
// speedup vs baseline: 1.2033x; 1.0348x over previous
#include <cuda_runtime.h>
#include <cuda_bf16.h>
#include <math.h>
#include <cstdint>

#define Nn 64
#define Tt 512
#define Dd 128
#define Hh 256
#define G4 1024
#define TC 512
#define ROWS (Nn*Tt)

// ================= static scratch =================
__device__ float g_gatesF[(size_t)ROWS * G4];
__device__ float g_gatesB[(size_t)ROWS * G4];
__device__ float g_hs0[(size_t)ROWS * TC];
__device__ float g_hs1[(size_t)ROWS * TC];
__device__ float g_scores[(size_t)Nn * Tt * Tt];
__device__ float g_cat[(size_t)ROWS * 1024];
__device__ float g_fc1[(size_t)ROWS * 50];
__device__ float g_fc2[(size_t)ROWS * 25];
__device__ float g_fc3[(size_t)ROWS * 10];
__device__ float g_mean[64];
__device__ float g_istd[64];
__device__ unsigned g_bcnt[8][64];
__device__ volatile unsigned g_bgen[8][64];

// h state as split bf16 [hi(256)|lo(256)] per batch row; double buffered, per dir
__device__ __align__(16) __nv_bfloat16 g_hsplit[2][2][Nn * 512];

// bf16 split buffers (K' = 3K)
__device__ __align__(16) __nv_bfloat16 g_xA[(size_t)ROWS * 384];
__device__ __align__(16) __nv_bfloat16 g_w0fB[(size_t)G4 * 384];
__device__ __align__(16) __nv_bfloat16 g_w0bB[(size_t)G4 * 384];
__device__ __align__(16) __nv_bfloat16 g_w1fB[(size_t)G4 * 1536];
__device__ __align__(16) __nv_bfloat16 g_w1bB[(size_t)G4 * 1536];
__device__ __align__(16) __nv_bfloat16 g_hs0A[(size_t)ROWS * 1536];
__device__ __align__(16) __nv_bfloat16 g_hs1A[(size_t)ROWS * 1536];
__device__ __align__(16) __nv_bfloat16 g_hs1B[(size_t)ROWS * 1536];
__device__ __align__(16) __nv_bfloat16 g_hsTB[(size_t)ROWS * 1536];
__device__ __align__(16) __nv_bfloat16 g_attnA[(size_t)ROWS * 1536];

// ================= per-(dir,bblk) grid barrier (16 CTAs each) =================
__device__ __forceinline__ void grid_sync_grp(int grp) {
    __syncthreads();
    if (threadIdx.x == 0) {
        __threadfence();
        unsigned gen = g_bgen[grp][0];
        if (atomicAdd(&g_bcnt[grp][0], 1) == 15) {
            g_bcnt[grp][0] = 0;
            __threadfence();
            g_bgen[grp][0] = gen + 1;
        } else {
            while (g_bgen[grp][0] == gen) { }
        }
    }
    __syncthreads();
}

// ================= HMMA helpers =================
__device__ __forceinline__ uint32_t smem_u32(const void* p) {
    uint32_t a;
    asm("{ .reg .u64 t; cvta.to.shared.u64 t, %1; cvt.u32.u64 %0, t; }" : "=r"(a) : "l"(p));
    return a;
}
__device__ __forceinline__ void ldsm_x4(uint32_t& r0, uint32_t& r1, uint32_t& r2, uint32_t& r3,
                                        uint32_t addr) {
    asm volatile("ldmatrix.sync.aligned.m8n8.x4.shared.b16 {%0,%1,%2,%3}, [%4];"
                 : "=r"(r0), "=r"(r1), "=r"(r2), "=r"(r3) : "r"(addr));
}
__device__ __forceinline__ void ldsm_x2(uint32_t& r0, uint32_t& r1, uint32_t addr) {
    asm volatile("ldmatrix.sync.aligned.m8n8.x2.shared.b16 {%0,%1}, [%2];"
                 : "=r"(r0), "=r"(r1) : "r"(addr));
}
__device__ __forceinline__ void mma16816(float* c, const uint32_t* a, const uint32_t* b) {
    asm volatile(
        "mma.sync.aligned.m16n8k16.row.col.f32.bf16.bf16.f32 "
        "{%0,%1,%2,%3}, {%4,%5,%6,%7}, {%8,%9}, {%0,%1,%2,%3};"
        : "+f"(c[0]), "+f"(c[1]), "+f"(c[2]), "+f"(c[3])
        : "r"(a[0]), "r"(a[1]), "r"(a[2]), "r"(a[3]), "r"(b[0]), "r"(b[1]));
}
#define CP16(dst, src) \
    asm volatile("cp.async.cg.shared.global [%0], [%1], 16;" :: "r"(dst), "l"(src))
#define CP_COMMIT() asm volatile("cp.async.commit_group;" ::: "memory")
#define CP_WAIT1()  asm volatile("cp.async.wait_group 1;" ::: "memory")
#define CP_WAIT0()  asm volatile("cp.async.wait_group 0;" ::: "memory")

// ================= HMMA bf16 GEMM, 2-stage cp.async pipeline =================
// C(MxN) = A(MxK')·B(NxK')^T. CTA 128x128, 8 warps (2m x 4n), K chunk 64.
#define SMSTRIDE 72
#define GS (128 * SMSTRIDE)                 // bf16 elems per matrix per stage
#define GEMM_SMEM (4 * GS * 2)              // bytes: 2 stages x (A+B)

__global__ __launch_bounds__(256)
void gemm_mma(const __nv_bfloat16* __restrict__ Ag, const __nv_bfloat16* __restrict__ Bg,
              const float* __restrict__ bias, float* __restrict__ Cg,
              int Kp, int ldc, long sA, long sB, long sC)
{
    extern __shared__ __nv_bfloat16 smbuf[];
    __nv_bfloat16* Abuf = smbuf;
    __nv_bfloat16* Bbuf = smbuf + 2 * GS;

    int tid = threadIdx.x;
    int wid = tid >> 5, lane = tid & 31;
    int warp_m = wid & 1;
    int warp_n = wid >> 1;

    const __nv_bfloat16* A = Ag + (long)blockIdx.z * sA + (long)blockIdx.y * 128 * Kp;
    const __nv_bfloat16* B = Bg + (long)blockIdx.z * sB + (long)blockIdx.x * 128 * Kp;
    float* C = Cg + (long)blockIdx.z * sC;

    uint32_t aBase = smem_u32(Abuf);
    uint32_t bBase = smem_u32(Bbuf);

    float acc[4][4][4];
#pragma unroll
    for (int mi = 0; mi < 4; mi++)
#pragma unroll
        for (int ni = 0; ni < 4; ni++)
#pragma unroll
            for (int q = 0; q < 4; q++) acc[mi][ni][q] = 0.f;

    int NC = Kp >> 6;

    // preload chunk 0 -> stage 0
    {
#pragma unroll
        for (int p = 0; p < 4; p++) {
            int idx = tid + p * 256;
            int row = idx >> 3, cg = (idx & 7) * 8;
            CP16(aBase + (row * SMSTRIDE + cg) * 2, A + (long)row * Kp + cg);
            CP16(bBase + (row * SMSTRIDE + cg) * 2, B + (long)row * Kp + cg);
        }
        CP_COMMIT();
    }

    for (int c = 0; c < NC; c++) {
        if (c + 1 < NC) {
            int s = (c + 1) & 1;
#pragma unroll
            for (int p = 0; p < 4; p++) {
                int idx = tid + p * 256;
                int row = idx >> 3, cg = (idx & 7) * 8;
                CP16(aBase + (s * GS + row * SMSTRIDE + cg) * 2,
                     A + (long)row * Kp + (c + 1) * 64 + cg);
                CP16(bBase + (s * GS + row * SMSTRIDE + cg) * 2,
                     B + (long)row * Kp + (c + 1) * 64 + cg);
            }
            CP_COMMIT();
            CP_WAIT1();
        } else {
            CP_WAIT0();
        }
        __syncthreads();

        uint32_t aS = aBase + (c & 1) * GS * 2;
        uint32_t bS = bBase + (c & 1) * GS * 2;
#pragma unroll
        for (int kk = 0; kk < 4; kk++) {
            int k0 = kk * 16;
            uint32_t af[4][4], bfr[4][2];
#pragma unroll
            for (int mi = 0; mi < 4; mi++) {
                int row = warp_m * 64 + mi * 16 + (lane & 15);
                int col = k0 + (lane >> 4) * 8;
                ldsm_x4(af[mi][0], af[mi][1], af[mi][2], af[mi][3],
                        aS + (row * SMSTRIDE + col) * 2);
            }
#pragma unroll
            for (int ni = 0; ni < 4; ni++) {
                int row = warp_n * 32 + ni * 8 + (lane & 7);
                int col = k0 + ((lane >> 3) & 1) * 8;
                ldsm_x2(bfr[ni][0], bfr[ni][1], bS + (row * SMSTRIDE + col) * 2);
            }
#pragma unroll
            for (int mi = 0; mi < 4; mi++)
#pragma unroll
                for (int ni = 0; ni < 4; ni++)
                    mma16816(acc[mi][ni], af[mi], bfr[ni]);
        }
        __syncthreads();
    }

    int m_base = blockIdx.y * 128 + warp_m * 64;
    int n_base = blockIdx.x * 128 + warp_n * 32;
    int r = lane >> 2, cp = (lane & 3) * 2;
#pragma unroll
    for (int mi = 0; mi < 4; mi++) {
#pragma unroll
        for (int ni = 0; ni < 4; ni++) {
            int m = m_base + mi * 16 + r;
            int n = n_base + ni * 8 + cp;
            float2 v0 = make_float2(acc[mi][ni][0], acc[mi][ni][1]);
            float2 v1 = make_float2(acc[mi][ni][2], acc[mi][ni][3]);
            if (bias) {
                float b0 = bias[n], b1 = bias[n + 1];
                v0.x += b0; v0.y += b1;
                v1.x += b0; v1.y += b1;
            }
            *(float2*)(C + (long)m * ldc + n) = v0;
            *(float2*)(C + (long)(m + 8) * ldc + n) = v1;
        }
    }
}

// ================= split-bf16 conversion =================
__global__ void conv_split(const float* __restrict__ src, __nv_bfloat16* __restrict__ dst,
                           int kshift, long total, int flavB)
{
    long i = (long)blockIdx.x * blockDim.x + threadIdx.x;
    if (i >= total) return;
    int K = 1 << kshift;
    long m = i >> kshift;
    int k = (int)(i & (K - 1));
    float x = src[i];
    __nv_bfloat16 hi = __float2bfloat16_rn(x);
    __nv_bfloat16 lo = __float2bfloat16_rn(x - __bfloat162float(hi));
    __nv_bfloat16* d = dst + m * 3 * K;
    d[k] = hi;
    if (flavB) { d[K + k] = lo; d[2 * K + k] = hi; }
    else       { d[K + k] = hi; d[2 * K + k] = lo; }
}

__global__ void transp_convB(const float* __restrict__ hs, __nv_bfloat16* __restrict__ dst)
{
    __shared__ float tile[32][33];
    int n = blockIdx.z;
    int s0 = blockIdx.y * 32, h0 = blockIdx.x * 32;
    int tx = threadIdx.x, ty = threadIdx.y;
    tile[ty][tx] = hs[((long)n * Tt + s0 + ty) * TC + h0 + tx];
    __syncthreads();
    float x = tile[tx][ty];
    __nv_bfloat16 hi = __float2bfloat16_rn(x);
    __nv_bfloat16 lo = __float2bfloat16_rn(x - __bfloat162float(hi));
    __nv_bfloat16* d = dst + (long)n * Tt * 1536 + (long)(h0 + ty) * 1536;
    int s = s0 + tx;
    d[s] = hi; d[512 + s] = lo; d[1024 + s] = hi;
}

// ================= persistent LSTM with HMMA recurrence, 2-D tiling =================
#define AS_STR 520
#define BS_STR 776
#define LSTM2_SMEM ((16 * AS_STR + 64 * BS_STR) * 2 + 3 * 16 * 64 * 4)

__global__ __launch_bounds__(256, 1)
void lstm_mma(const float* __restrict__ gatesF, const float* __restrict__ gatesB,
              const float* __restrict__ whhF, const float* __restrict__ whhB,
              float* __restrict__ hs_out)
{
    extern __shared__ char smraw[];
    __nv_bfloat16* As = (__nv_bfloat16*)smraw;
    __nv_bfloat16* Bs = As + 16 * AS_STR;
    float* gsm   = (float*)(Bs + 64 * BS_STR);
    float* ssum0 = gsm + 16 * 64;
    float* ssum1 = ssum0 + 16 * 64;

    int bx = blockIdx.x;
    int dir  = bx >> 6;
    int bblk = (bx >> 4) & 3;
    int cblk = bx & 15;
    int grp = dir * 4 + bblk;
    int b0 = bblk * 16;
    int jbase = cblk * 16;
    int tid = threadIdx.x;
    int wid = tid >> 5, lane = tid & 31;

    const float* W     = dir ? whhB : whhF;
    const float* gates = dir ? gatesB : gatesF;

    for (int i = tid; i < 64 * 768; i += 256) {
        int r = i / 768, k = i - r * 768;
        int j = jbase + (r >> 2);
        int g = r & 3;
        int korig = k & 255;
        float w = W[((long)(g * Hh + j)) * Hh + korig];
        __nv_bfloat16 hi = __float2bfloat16_rn(w);
        __nv_bfloat16 v;
        if (k >= 256 && k < 512) v = __float2bfloat16_rn(w - __bfloat162float(hi));
        else v = hi;
        Bs[r * BS_STR + k] = v;
    }
    __syncthreads();

    uint32_t aB = smem_u32(As);
    uint32_t bB = smem_u32(Bs);
    int wn = (wid & 3) * 16;
    int kh = wid >> 2;
    float* sdst = kh ? ssum1 : ssum0;

    uint32_t breg[24][4];
#pragma unroll
    for (int si = 0; si < 24; si++) {
        int s = kh * 24 + si;
        int rowB = wn + (lane & 7) + ((lane >> 4) << 3);
        int colB = s * 16 + (((lane >> 3) & 1) << 3);
        ldsm_x4(breg[si][0], breg[si][1], breg[si][2], breg[si][3],
                bB + (rowB * BS_STR + colB) * 2);
    }

    int b_local = tid >> 4, u = tid & 15;
    int bglob = b0 + b_local;
    int j = jbase + u;
    {
        __nv_bfloat16 z = __float2bfloat16_rn(0.f);
        g_hsplit[0][dir][bglob * 512 + j] = z;
        g_hsplit[0][dir][bglob * 512 + 256 + j] = z;
    }
    float c = 0.f;
    grid_sync_grp(grp);

    for (int t = 0; t < Tt; t++) {
        const __nv_bfloat16* hin = g_hsplit[t & 1][dir];
        int tin = dir ? (Tt - 1 - t) : t;

        const int4* src = (const int4*)(hin + (long)b0 * 512);
#pragma unroll
        for (int i = 0; i < 4; i++) {
            int idx = tid + i * 256;
            int row = idx >> 6, ch = idx & 63;
            int4 v = __ldcg(src + row * 64 + ch);
            *(int4*)(As + row * AS_STR + ch * 8) = v;
        }
        {
            int bl = tid >> 4;
            int g  = (tid >> 2) & 3;
            int q  = tid & 3;
            float4 gv = __ldg((const float4*)(gates + ((long)(b0 + bl) * Tt + tin) * G4
                                              + g * Hh + jbase + q * 4));
            gsm[bl * 64 + (q * 4 + 0) * 4 + g] = gv.x;
            gsm[bl * 64 + (q * 4 + 1) * 4 + g] = gv.y;
            gsm[bl * 64 + (q * 4 + 2) * 4 + g] = gv.z;
            gsm[bl * 64 + (q * 4 + 3) * 4 + g] = gv.w;
        }
        __syncthreads();

        float acc0[4] = {0.f, 0.f, 0.f, 0.f};
        float acc1[4] = {0.f, 0.f, 0.f, 0.f};
#pragma unroll
        for (int si = 0; si < 24; si++) {
            int s = kh * 24 + si;
            int kc = (s < 32) ? (s & 15) * 16 : 256 + (s - 32) * 16;
            uint32_t af[4];
            ldsm_x4(af[0], af[1], af[2], af[3],
                    aB + (((lane & 15)) * AS_STR + kc + (lane >> 4) * 8) * 2);
            uint32_t bf0[2] = {breg[si][0], breg[si][1]};
            uint32_t bf1[2] = {breg[si][2], breg[si][3]};
            mma16816(acc0, af, bf0);
            mma16816(acc1, af, bf1);
        }

        {
            int r = lane >> 2, cp = (lane & 3) * 2;
            int m1 = r, m2 = r + 8;
            *(float2*)&sdst[m1 * 64 + wn + cp]     = make_float2(acc0[0], acc0[1]);
            *(float2*)&sdst[m2 * 64 + wn + cp]     = make_float2(acc0[2], acc0[3]);
            *(float2*)&sdst[m1 * 64 + wn + 8 + cp] = make_float2(acc1[0], acc1[1]);
            *(float2*)&sdst[m2 * 64 + wn + 8 + cp] = make_float2(acc1[2], acc1[3]);
        }
        __syncthreads();

        int base = b_local * 64 + u * 4;
        float gi = gsm[base + 0] + ssum0[base + 0] + ssum1[base + 0];
        float gf = gsm[base + 1] + ssum0[base + 1] + ssum1[base + 1];
        float gg = gsm[base + 2] + ssum0[base + 2] + ssum1[base + 2];
        float go = gsm[base + 3] + ssum0[base + 3] + ssum1[base + 3];

        float ii = 1.f / (1.f + expf(-gi));
        float ff = 1.f / (1.f + expf(-gf));
        float tg = tanhf(gg);
        float oo = 1.f / (1.f + expf(-go));
        c = ff * c + ii * tg;
        float h = oo * tanhf(c);

        __nv_bfloat16 hi = __float2bfloat16_rn(h);
        __nv_bfloat16 lo = __float2bfloat16_rn(h - __bfloat162float(hi));
        __nv_bfloat16* hnext = g_hsplit[(t + 1) & 1][dir];
        hnext[bglob * 512 + j] = hi;
        hnext[bglob * 512 + 256 + j] = lo;
        hs_out[((long)bglob * Tt + tin) * TC + dir * Hh + j] = h;

        grid_sync_grp(grp);
    }
}

// ================= misc =================
__global__ void copy_right(const float* __restrict__ hs, float* __restrict__ cat) {
    long i = (long)blockIdx.x * blockDim.x + threadIdx.x;
    if (i < (long)ROWS * TC) {
        long m = i / TC, j = i % TC;
        cat[m * 1024 + 512 + j] = hs[i];
    }
}

__global__ void softmax_rows(const float* __restrict__ S, __nv_bfloat16* __restrict__ dst) {
    const float* row = S + (long)blockIdx.x * Tt;
    __nv_bfloat16* d = dst + (long)blockIdx.x * 1536;
    int tid = threadIdx.x;   // 128
    __shared__ float red[4];

    float mx = -1e30f;
    for (int j = tid; j < Tt; j += 128) mx = fmaxf(mx, row[j]);
#pragma unroll
    for (int o = 16; o; o >>= 1) mx = fmaxf(mx, __shfl_xor_sync(0xffffffffu, mx, o));
    if ((tid & 31) == 0) red[tid >> 5] = mx;
    __syncthreads();
    mx = fmaxf(fmaxf(red[0], red[1]), fmaxf(red[2], red[3]));

    float sum = 0.f;
    float e[4];
#pragma unroll
    for (int q = 0; q < 4; q++) {
        e[q] = expf(row[tid + q * 128] - mx);
        sum += e[q];
    }
#pragma unroll
    for (int o = 16; o; o >>= 1) sum += __shfl_xor_sync(0xffffffffu, sum, o);
    __syncthreads();
    if ((tid & 31) == 0) red[tid >> 5] = sum;
    __syncthreads();
    sum = red[0] + red[1] + red[2] + red[3];
    float inv = 1.f / sum;
#pragma unroll
    for (int q = 0; q < 4; q++) {
        int jj = tid + q * 128;
        float p = e[q] * inv;
        __nv_bfloat16 hi = __float2bfloat16_rn(p);
        __nv_bfloat16 lo = __float2bfloat16_rn(p - __bfloat162float(hi));
        d[jj] = hi; d[512 + jj] = hi; d[1024 + jj] = lo;
    }
}

__global__ void bn_stats(const float* __restrict__ Y, float* __restrict__ mean,
                         float* __restrict__ istd) {
    int ch = blockIdx.x;
    int tid = threadIdx.x;
    __shared__ float rs[8], rq[8];
    float s = 0.f, q = 0.f;
    for (int i = tid; i < Nn * Tt; i += 256) {
        int n = i >> 9, p = i & 511;
        float v = Y[(long)n * 25600 + ch * 512 + p];
        s += v; q += v * v;
    }
#pragma unroll
    for (int o = 16; o; o >>= 1) { s += __shfl_xor_sync(0xffffffffu, s, o); q += __shfl_xor_sync(0xffffffffu, q, o); }
    if ((tid & 31) == 0) { rs[tid >> 5] = s; rq[tid >> 5] = q; }
    __syncthreads();
    if (tid == 0) {
        s = 0.f; q = 0.f;
        for (int w = 0; w < 8; w++) { s += rs[w]; q += rq[w]; }
        float m = s / (float)(Nn * Tt);
        float var = q / (float)(Nn * Tt) - m * m;
        mean[ch] = m;
        istd[ch] = rsqrtf(var + 1e-5f);
    }
}

__global__ void bn_apply(float* __restrict__ Y, const float* __restrict__ mean,
                         const float* __restrict__ istd, const float* __restrict__ gam,
                         const float* __restrict__ bet) {
    long i = (long)blockIdx.x * blockDim.x + threadIdx.x;
    if (i < (long)ROWS * 50) {
        long r = i % 25600;
        int ch = (int)(r >> 9);
        Y[i] = (Y[i] - mean[ch]) * istd[ch] * gam[ch] + bet[ch];
    }
}

__global__ void gemm_bt64(const float* __restrict__ A, const float* __restrict__ B,
                          const float* __restrict__ bias, float* __restrict__ C,
                          int M, int N, int K, int ldc, int relu)
{
    __shared__ float As[16][64];
    __shared__ float Bs[16][64];
    int tx = threadIdx.x, ty = threadIdx.y;
    int tid = ty * 16 + tx;
    int m0 = blockIdx.y * 64, n0 = blockIdx.x * 64;

    float acc[4][4];
#pragma unroll
    for (int i = 0; i < 4; i++)
#pragma unroll
        for (int j = 0; j < 4; j++) acc[i][j] = 0.f;

    int lrow = tid >> 2;
    int lk   = (tid & 3) * 4;

    for (int k0 = 0; k0 < K; k0 += 16) {
        {
            float4 v = make_float4(0.f, 0.f, 0.f, 0.f);
            int m = m0 + lrow;
            if (m < M) v = *(const float4*)(A + (long)m * K + k0 + lk);
            As[lk + 0][lrow] = v.x; As[lk + 1][lrow] = v.y;
            As[lk + 2][lrow] = v.z; As[lk + 3][lrow] = v.w;
        }
        {
            float4 v = make_float4(0.f, 0.f, 0.f, 0.f);
            int n = n0 + lrow;
            if (n < N) v = *(const float4*)(B + (long)n * K + k0 + lk);
            Bs[lk + 0][lrow] = v.x; Bs[lk + 1][lrow] = v.y;
            Bs[lk + 2][lrow] = v.z; Bs[lk + 3][lrow] = v.w;
        }
        __syncthreads();
#pragma unroll
        for (int kk = 0; kk < 16; kk++) {
            float4 a = *(const float4*)&As[kk][ty * 4];
            float4 b = *(const float4*)&Bs[kk][tx * 4];
            acc[0][0] += a.x * b.x; acc[0][1] += a.x * b.y; acc[0][2] += a.x * b.z; acc[0][3] += a.x * b.w;
            acc[1][0] += a.y * b.x; acc[1][1] += a.y * b.y; acc[1][2] += a.y * b.z; acc[1][3] += a.y * b.w;
            acc[2][0] += a.z * b.x; acc[2][1] += a.z * b.y; acc[2][2] += a.z * b.z; acc[2][3] += a.z * b.w;
            acc[3][0] += a.w * b.x; acc[3][1] += a.w * b.y; acc[3][2] += a.w * b.z; acc[3][3] += a.w * b.w;
        }
        __syncthreads();
    }
#pragma unroll
    for (int i = 0; i < 4; i++) {
        int m = m0 + ty * 4 + i;
        if (m >= M) continue;
#pragma unroll
        for (int j = 0; j < 4; j++) {
            int n = n0 + tx * 4 + j;
            if (n >= N) continue;
            float v = acc[i][j];
            if (bias) v += bias[n];
            if (relu) v = fmaxf(v, 0.f);
            C[(long)m * ldc + n] = v;
        }
    }
}

template <int K, int N, bool RELU>
__global__ void small_fc(const float* __restrict__ X, const float* __restrict__ W,
                         const float* __restrict__ bias, float* __restrict__ Y) {
    __shared__ float xs[128 * K];
    __shared__ float ws[N * K];
    __shared__ float bs[N];
    int tid = threadIdx.x;
    long m0 = (long)blockIdx.x * 128;
    for (int i = tid; i < N * K; i += 128) ws[i] = W[i];
    for (int i = tid; i < N; i += 128) bs[i] = bias[i];
    for (int i = tid; i < 128 * K; i += 128) xs[i] = X[m0 * K + i];
    __syncthreads();
    long m = m0 + tid;
#pragma unroll
    for (int j = 0; j < N; j++) {
        float acc = bs[j];
#pragma unroll
        for (int k = 0; k < K; k++) acc += xs[tid * K + k] * ws[j * K + k];
        if (RELU) acc = fmaxf(acc, 0.f);
        Y[m * N + j] = acc;
    }
}

// ================= host orchestration =================
extern "C" void kernel_launch(void* const* d_in, const int* in_sizes, int n_in,
                              void* d_out, int out_size)
{
    const float* x     = (const float*)d_in[0];
    const float* wih0f = (const float*)d_in[1];
    const float* whh0f = (const float*)d_in[2];
    const float* b0f   = (const float*)d_in[3];
    const float* wih0b = (const float*)d_in[4];
    const float* whh0b = (const float*)d_in[5];
    const float* b0b   = (const float*)d_in[6];
    const float* wih1f = (const float*)d_in[7];
    const float* whh1f = (const float*)d_in[8];
    const float* b1f   = (const float*)d_in[9];
    const float* wih1b = (const float*)d_in[10];
    const float* whh1b = (const float*)d_in[11];
    const float* b1b   = (const float*)d_in[12];
    const float* fc1w  = (const float*)d_in[13];
    const float* fc1b  = (const float*)d_in[14];
    const float* bng   = (const float*)d_in[15];
    const float* bnb   = (const float*)d_in[16];
    const float* fc2w  = (const float*)d_in[17];
    const float* fc2b  = (const float*)d_in[18];
    const float* fc3w  = (const float*)d_in[19];
    const float* fc3b  = (const float*)d_in[20];
    const float* fc4w  = (const float*)d_in[21];
    const float* fc4b  = (const float*)d_in[22];
    float* out = (float*)d_out;

    float *gF, *gB, *hs0, *hs1, *sc, *cat, *f1, *f2, *f3, *mean, *istd;
    __nv_bfloat16 *xA, *w0fB, *w0bB, *w1fB, *w1bB, *hs0A, *hs1A, *hs1B, *hsTB, *attnA;
    cudaGetSymbolAddress((void**)&gF,   g_gatesF);
    cudaGetSymbolAddress((void**)&gB,   g_gatesB);
    cudaGetSymbolAddress((void**)&hs0,  g_hs0);
    cudaGetSymbolAddress((void**)&hs1,  g_hs1);
    cudaGetSymbolAddress((void**)&sc,   g_scores);
    cudaGetSymbolAddress((void**)&cat,  g_cat);
    cudaGetSymbolAddress((void**)&f1,   g_fc1);
    cudaGetSymbolAddress((void**)&f2,   g_fc2);
    cudaGetSymbolAddress((void**)&f3,   g_fc3);
    cudaGetSymbolAddress((void**)&mean, g_mean);
    cudaGetSymbolAddress((void**)&istd, g_istd);
    cudaGetSymbolAddress((void**)&xA,    g_xA);
    cudaGetSymbolAddress((void**)&w0fB,  g_w0fB);
    cudaGetSymbolAddress((void**)&w0bB,  g_w0bB);
    cudaGetSymbolAddress((void**)&w1fB,  g_w1fB);
    cudaGetSymbolAddress((void**)&w1bB,  g_w1bB);
    cudaGetSymbolAddress((void**)&hs0A,  g_hs0A);
    cudaGetSymbolAddress((void**)&hs1A,  g_hs1A);
    cudaGetSymbolAddress((void**)&hs1B,  g_hs1B);
    cudaGetSymbolAddress((void**)&hsTB,  g_hsTB);
    cudaGetSymbolAddress((void**)&attnA, g_attnA);

    cudaFuncSetAttribute(lstm_mma, cudaFuncAttributeMaxDynamicSharedMemorySize, LSTM2_SMEM);
    cudaFuncSetAttribute(gemm_mma, cudaFuncAttributeMaxDynamicSharedMemorySize, GEMM_SMEM);

    // ---- conversions ----
    conv_split<<<(int)(((long)ROWS * Dd + 255) / 256), 256>>>(x, xA, 7, (long)ROWS * Dd, 0);
    conv_split<<<(G4 * Dd + 255) / 256, 256>>>(wih0f, w0fB, 7, (long)G4 * Dd, 1);
    conv_split<<<(G4 * Dd + 255) / 256, 256>>>(wih0b, w0bB, 7, (long)G4 * Dd, 1);
    conv_split<<<(G4 * TC + 255) / 256, 256>>>(wih1f, w1fB, 9, (long)G4 * TC, 1);
    conv_split<<<(G4 * TC + 255) / 256, 256>>>(wih1b, w1bB, 9, (long)G4 * TC, 1);

    // ---- layer 0 ----
    gemm_mma<<<dim3(8, 256), 256, GEMM_SMEM>>>(xA, w0fB, b0f, gF, 384, G4, 0, 0, 0);
    gemm_mma<<<dim3(8, 256), 256, GEMM_SMEM>>>(xA, w0bB, b0b, gB, 384, G4, 0, 0, 0);
    lstm_mma<<<128, 256, LSTM2_SMEM>>>(gF, gB, whh0f, whh0b, hs0);

    // ---- layer 1 ----
    conv_split<<<(int)(((long)ROWS * TC + 255) / 256), 256>>>(hs0, hs0A, 9, (long)ROWS * TC, 0);
    gemm_mma<<<dim3(8, 256), 256, GEMM_SMEM>>>(hs0A, w1fB, b1f, gF, 1536, G4, 0, 0, 0);
    gemm_mma<<<dim3(8, 256), 256, GEMM_SMEM>>>(hs0A, w1bB, b1b, gB, 1536, G4, 0, 0, 0);
    lstm_mma<<<128, 256, LSTM2_SMEM>>>(gF, gB, whh1f, whh1b, hs1);

    // ---- attention ----
    conv_split<<<(int)(((long)ROWS * TC + 255) / 256), 256>>>(hs1, hs1A, 9, (long)ROWS * TC, 0);
    conv_split<<<(int)(((long)ROWS * TC + 255) / 256), 256>>>(hs1, hs1B, 9, (long)ROWS * TC, 1);
    transp_convB<<<dim3(16, 16, Nn), dim3(32, 32)>>>(hs1, hsTB);

    long sAB = (long)Tt * 1536;
    gemm_mma<<<dim3(4, 4, Nn), 256, GEMM_SMEM>>>(hs1A, hs1B, nullptr, sc, 1536, Tt,
                                                 sAB, sAB, (long)Tt * Tt);
    softmax_rows<<<Nn * Tt, 128>>>(sc, attnA);
    gemm_mma<<<dim3(4, 4, Nn), 256, GEMM_SMEM>>>(attnA, hsTB, nullptr, cat, 1536, 1024,
                                                 sAB, sAB, (long)Tt * 1024);
    copy_right<<<(int)(((long)ROWS * TC + 255) / 256), 256>>>(hs1, cat);

    // ---- head ----
    gemm_bt64<<<dim3(1, 512), dim3(16, 16)>>>(cat, fc1w, fc1b, f1, ROWS, 50, 1024, 50, 1);
    bn_stats<<<50, 256>>>(f1, mean, istd);
    bn_apply<<<(int)(((long)ROWS * 50 + 255) / 256), 256>>>(f1, mean, istd, bng, bnb);
    small_fc<50, 25, true ><<<ROWS / 128, 128>>>(f1, fc2w, fc2b, f2);
    small_fc<25, 10, true ><<<ROWS / 128, 128>>>(f2, fc3w, fc3b, f3);
    small_fc<10, 2,  false><<<ROWS / 128, 128>>>(f3, fc4w, fc4b, out);
}

// round 15
// speedup vs baseline: 1.2153x; 1.0100x over previous
#include <cuda_runtime.h>
#include <cuda_bf16.h>
#include <math.h>
#include <cstdint>

#define Nn 64
#define Tt 512
#define Dd 128
#define Hh 256
#define G4 1024
#define TC 512
#define ROWS (Nn*Tt)

// ================= static scratch =================
__device__ float g_gatesF[(size_t)ROWS * G4];
__device__ float g_gatesB[(size_t)ROWS * G4];
__device__ float g_hs0[(size_t)ROWS * TC];
__device__ float g_hs1[(size_t)ROWS * TC];
__device__ float g_scores[(size_t)Nn * Tt * Tt];
__device__ float g_fc1[(size_t)ROWS * 50];
__device__ float g_fc2[(size_t)ROWS * 25];
__device__ float g_fc3[(size_t)ROWS * 10];
__device__ float g_mean[64];
__device__ float g_istd[64];
__device__ unsigned g_bcnt[8][64];
__device__ volatile unsigned g_bgen[8][64];

// h state as split bf16 [hi(256)|lo(256)] per batch row; double buffered, per dir
__device__ __align__(16) __nv_bfloat16 g_hsplit[2][2][Nn * 512];

// bf16 split buffers (K' = 3K)
__device__ __align__(16) __nv_bfloat16 g_xA[(size_t)ROWS * 384];
__device__ __align__(16) __nv_bfloat16 g_w0fB[(size_t)G4 * 384];
__device__ __align__(16) __nv_bfloat16 g_w0bB[(size_t)G4 * 384];
__device__ __align__(16) __nv_bfloat16 g_w1fB[(size_t)G4 * 1536];
__device__ __align__(16) __nv_bfloat16 g_w1bB[(size_t)G4 * 1536];
__device__ __align__(16) __nv_bfloat16 g_hs0A[(size_t)ROWS * 1536];
__device__ __align__(16) __nv_bfloat16 g_hs1A[(size_t)ROWS * 1536];
__device__ __align__(16) __nv_bfloat16 g_hs1B[(size_t)ROWS * 1536];
__device__ __align__(16) __nv_bfloat16 g_hsTB[(size_t)ROWS * 1536];
__device__ __align__(16) __nv_bfloat16 g_attnA[(size_t)ROWS * 1536];
__device__ __align__(16) __nv_bfloat16 g_catA[(size_t)ROWS * 3072];    // flavor A, K=1024
__device__ __align__(16) __nv_bfloat16 g_fc1wB[(size_t)128 * 3072];    // padded, flavor B

// ================= per-(dir,bblk) grid barrier (16 CTAs each) =================
__device__ __forceinline__ void grid_sync_grp(int grp) {
    __syncthreads();
    if (threadIdx.x == 0) {
        __threadfence();
        unsigned gen = g_bgen[grp][0];
        if (atomicAdd(&g_bcnt[grp][0], 1) == 15) {
            g_bcnt[grp][0] = 0;
            __threadfence();
            g_bgen[grp][0] = gen + 1;
        } else {
            while (g_bgen[grp][0] == gen) { }
        }
    }
    __syncthreads();
}

// ================= HMMA helpers =================
__device__ __forceinline__ uint32_t smem_u32(const void* p) {
    uint32_t a;
    asm("{ .reg .u64 t; cvta.to.shared.u64 t, %1; cvt.u32.u64 %0, t; }" : "=r"(a) : "l"(p));
    return a;
}
__device__ __forceinline__ void ldsm_x4(uint32_t& r0, uint32_t& r1, uint32_t& r2, uint32_t& r3,
                                        uint32_t addr) {
    asm volatile("ldmatrix.sync.aligned.m8n8.x4.shared.b16 {%0,%1,%2,%3}, [%4];"
                 : "=r"(r0), "=r"(r1), "=r"(r2), "=r"(r3) : "r"(addr));
}
__device__ __forceinline__ void ldsm_x2(uint32_t& r0, uint32_t& r1, uint32_t addr) {
    asm volatile("ldmatrix.sync.aligned.m8n8.x2.shared.b16 {%0,%1}, [%2];"
                 : "=r"(r0), "=r"(r1) : "r"(addr));
}
__device__ __forceinline__ void mma16816(float* c, const uint32_t* a, const uint32_t* b) {
    asm volatile(
        "mma.sync.aligned.m16n8k16.row.col.f32.bf16.bf16.f32 "
        "{%0,%1,%2,%3}, {%4,%5,%6,%7}, {%8,%9}, {%0,%1,%2,%3};"
        : "+f"(c[0]), "+f"(c[1]), "+f"(c[2]), "+f"(c[3])
        : "r"(a[0]), "r"(a[1]), "r"(a[2]), "r"(a[3]), "r"(b[0]), "r"(b[1]));
}
#define CP16(dst, src) \
    asm volatile("cp.async.cg.shared.global [%0], [%1], 16;" :: "r"(dst), "l"(src))
#define CP_COMMIT() asm volatile("cp.async.commit_group;" ::: "memory")
#define CP_WAIT2()  asm volatile("cp.async.wait_group 2;" ::: "memory")

// ================= HMMA bf16 GEMM, 3-stage cp.async pipeline =================
// C(MxN) = A(MxK')·B(NxK')^T. CTA 128x128, 8 warps (2m x 4n), K chunk 64.
// Optional outputs: fp32 C (with bias/relu, cols < nmax) OR split-A bf16 CA
// (writes hi at [m*3*ldcA+n], hi at [+ldcA], lo at [+2*ldcA]).
#define SMSTRIDE 72
#define GS (128 * SMSTRIDE)                    // bf16 elems per matrix per stage
#define STG_ELEMS (2 * GS)                     // A+B per stage
#define GEMM_SMEM (3 * STG_ELEMS * 2)          // bytes

__global__ __launch_bounds__(256)
void gemm_mma(const __nv_bfloat16* __restrict__ Ag, const __nv_bfloat16* __restrict__ Bg,
              const float* __restrict__ bias, float* __restrict__ Cg,
              __nv_bfloat16* __restrict__ CAg,
              int Kp, int ldc, int ldcA, long sA, long sB, long sC,
              int nmax, int relu)
{
    extern __shared__ __nv_bfloat16 smbuf[];

    int tid = threadIdx.x;
    int wid = tid >> 5, lane = tid & 31;
    int warp_m = wid & 1;
    int warp_n = wid >> 1;

    const __nv_bfloat16* A = Ag + (long)blockIdx.z * sA + (long)blockIdx.y * 128 * Kp;
    const __nv_bfloat16* B = Bg + (long)blockIdx.z * sB + (long)blockIdx.x * 128 * Kp;
    float* C = Cg ? (Cg + (long)blockIdx.z * sC) : nullptr;
    __nv_bfloat16* CA = CAg ? (CAg + (long)blockIdx.z * sC * 3) : nullptr;

    uint32_t base = smem_u32(smbuf);

    float acc[4][4][4];
#pragma unroll
    for (int mi = 0; mi < 4; mi++)
#pragma unroll
        for (int ni = 0; ni < 4; ni++)
#pragma unroll
            for (int q = 0; q < 4; q++) acc[mi][ni][q] = 0.f;

    int NC = Kp >> 6;

    // prologue: preload chunks 0 and 1 into stages 0, 1
#pragma unroll
    for (int pc = 0; pc < 2; pc++) {
        if (pc < NC) {
            uint32_t aS = base + (pc * STG_ELEMS) * 2;
            uint32_t bS = aS + GS * 2;
#pragma unroll
            for (int p = 0; p < 4; p++) {
                int idx = tid + p * 256;
                int row = idx >> 3, cg = (idx & 7) * 8;
                CP16(aS + (row * SMSTRIDE + cg) * 2, A + (long)row * Kp + pc * 64 + cg);
                CP16(bS + (row * SMSTRIDE + cg) * 2, B + (long)row * Kp + pc * 64 + cg);
            }
        }
        CP_COMMIT();
    }

    for (int c = 0; c < NC; c++) {
        // issue chunk c+2 into stage (c+2)%3 (or an empty group)
        if (c + 2 < NC) {
            int s = (c + 2) % 3;
            uint32_t aS = base + (s * STG_ELEMS) * 2;
            uint32_t bS = aS + GS * 2;
#pragma unroll
            for (int p = 0; p < 4; p++) {
                int idx = tid + p * 256;
                int row = idx >> 3, cg = (idx & 7) * 8;
                CP16(aS + (row * SMSTRIDE + cg) * 2, A + (long)row * Kp + (c + 2) * 64 + cg);
                CP16(bS + (row * SMSTRIDE + cg) * 2, B + (long)row * Kp + (c + 2) * 64 + cg);
            }
        }
        CP_COMMIT();
        CP_WAIT2();          // chunk c's group is now complete
        __syncthreads();

        int s = c % 3;
        uint32_t aS = base + (s * STG_ELEMS) * 2;
        uint32_t bS = aS + GS * 2;
#pragma unroll
        for (int kk = 0; kk < 4; kk++) {
            int k0 = kk * 16;
            uint32_t af[4][4], bfr[4][2];
#pragma unroll
            for (int mi = 0; mi < 4; mi++) {
                int row = warp_m * 64 + mi * 16 + (lane & 15);
                int col = k0 + (lane >> 4) * 8;
                ldsm_x4(af[mi][0], af[mi][1], af[mi][2], af[mi][3],
                        aS + (row * SMSTRIDE + col) * 2);
            }
#pragma unroll
            for (int ni = 0; ni < 4; ni++) {
                int row = warp_n * 32 + ni * 8 + (lane & 7);
                int col = k0 + ((lane >> 3) & 1) * 8;
                ldsm_x2(bfr[ni][0], bfr[ni][1], bS + (row * SMSTRIDE + col) * 2);
            }
#pragma unroll
            for (int mi = 0; mi < 4; mi++)
#pragma unroll
                for (int ni = 0; ni < 4; ni++)
                    mma16816(acc[mi][ni], af[mi], bfr[ni]);
        }
        __syncthreads();
    }

    int m_base = blockIdx.y * 128 + warp_m * 64;
    int n_base = blockIdx.x * 128 + warp_n * 32;
    int r = lane >> 2, cp = (lane & 3) * 2;
#pragma unroll
    for (int mi = 0; mi < 4; mi++) {
#pragma unroll
        for (int ni = 0; ni < 4; ni++) {
            int m = m_base + mi * 16 + r;
            int n = n_base + ni * 8 + cp;
            if (n >= nmax) continue;
            float2 v0 = make_float2(acc[mi][ni][0], acc[mi][ni][1]);
            float2 v1 = make_float2(acc[mi][ni][2], acc[mi][ni][3]);
            if (bias) {
                float b0 = bias[n], b1 = bias[n + 1];
                v0.x += b0; v0.y += b1;
                v1.x += b0; v1.y += b1;
            }
            if (relu) {
                v0.x = fmaxf(v0.x, 0.f); v0.y = fmaxf(v0.y, 0.f);
                v1.x = fmaxf(v1.x, 0.f); v1.y = fmaxf(v1.y, 0.f);
            }
            if (C) {
                *(float2*)(C + (long)m * ldc + n) = v0;
                *(float2*)(C + (long)(m + 8) * ldc + n) = v1;
            }
            if (CA) {
#pragma unroll
                for (int hh = 0; hh < 2; hh++) {
                    int mm = m + hh * 8;
                    float vx = hh ? v1.x : v0.x;
                    float vy = hh ? v1.y : v0.y;
                    __nv_bfloat16 hx = __float2bfloat16_rn(vx);
                    __nv_bfloat16 lx = __float2bfloat16_rn(vx - __bfloat162float(hx));
                    __nv_bfloat16 hy = __float2bfloat16_rn(vy);
                    __nv_bfloat16 ly = __float2bfloat16_rn(vy - __bfloat162float(hy));
                    __nv_bfloat16* d = CA + (long)mm * 3 * ldcA + n;
                    d[0] = hx; d[1] = hy;
                    d[ldcA] = hx; d[ldcA + 1] = hy;
                    d[2 * ldcA] = lx; d[2 * ldcA + 1] = ly;
                }
            }
        }
    }
}

// ================= split-bf16 conversion =================
__global__ void conv_split(const float* __restrict__ src, __nv_bfloat16* __restrict__ dst,
                           int kshift, long total, int flavB)
{
    long i = (long)blockIdx.x * blockDim.x + threadIdx.x;
    if (i >= total) return;
    int K = 1 << kshift;
    long m = i >> kshift;
    int k = (int)(i & (K - 1));
    float x = src[i];
    __nv_bfloat16 hi = __float2bfloat16_rn(x);
    __nv_bfloat16 lo = __float2bfloat16_rn(x - __bfloat162float(hi));
    __nv_bfloat16* d = dst + m * 3 * K;
    d[k] = hi;
    if (flavB) { d[K + k] = lo; d[2 * K + k] = hi; }
    else       { d[K + k] = hi; d[2 * K + k] = lo; }
}

// padded fc1 weight: 128 rows x K=1024, rows >= 50 zero; flavor B
__global__ void conv_split_pad50(const float* __restrict__ src, __nv_bfloat16* __restrict__ dst)
{
    int i = blockIdx.x * blockDim.x + threadIdx.x;
    if (i >= 128 * 1024) return;
    int row = i >> 10, k = i & 1023;
    float x = (row < 50) ? src[row * 1024 + k] : 0.f;
    __nv_bfloat16 hi = __float2bfloat16_rn(x);
    __nv_bfloat16 lo = __float2bfloat16_rn(x - __bfloat162float(hi));
    __nv_bfloat16* d = dst + (long)row * 3072;
    d[k] = hi; d[1024 + k] = lo; d[2048 + k] = hi;
}

__global__ void transp_convB(const float* __restrict__ hs, __nv_bfloat16* __restrict__ dst)
{
    __shared__ float tile[32][33];
    int n = blockIdx.z;
    int s0 = blockIdx.y * 32, h0 = blockIdx.x * 32;
    int tx = threadIdx.x, ty = threadIdx.y;
    tile[ty][tx] = hs[((long)n * Tt + s0 + ty) * TC + h0 + tx];
    __syncthreads();
    float x = tile[tx][ty];
    __nv_bfloat16 hi = __float2bfloat16_rn(x);
    __nv_bfloat16 lo = __float2bfloat16_rn(x - __bfloat162float(hi));
    __nv_bfloat16* d = dst + (long)n * Tt * 1536 + (long)(h0 + ty) * 1536;
    int s = s0 + tx;
    d[s] = hi; d[512 + s] = lo; d[1024 + s] = hi;
}

// ================= persistent LSTM with HMMA recurrence, 2-D tiling =================
#define AS_STR 520
#define BS_STR 776
#define LSTM2_SMEM ((16 * AS_STR + 64 * BS_STR) * 2 + 3 * 16 * 64 * 4)

__global__ __launch_bounds__(256, 1)
void lstm_mma(const float* __restrict__ gatesF, const float* __restrict__ gatesB,
              const float* __restrict__ whhF, const float* __restrict__ whhB,
              float* __restrict__ hs_out)
{
    extern __shared__ char smraw[];
    __nv_bfloat16* As = (__nv_bfloat16*)smraw;
    __nv_bfloat16* Bs = As + 16 * AS_STR;
    float* gsm   = (float*)(Bs + 64 * BS_STR);
    float* ssum0 = gsm + 16 * 64;
    float* ssum1 = ssum0 + 16 * 64;

    int bx = blockIdx.x;
    int dir  = bx >> 6;
    int bblk = (bx >> 4) & 3;
    int cblk = bx & 15;
    int grp = dir * 4 + bblk;
    int b0 = bblk * 16;
    int jbase = cblk * 16;
    int tid = threadIdx.x;
    int wid = tid >> 5, lane = tid & 31;

    const float* W     = dir ? whhB : whhF;
    const float* gates = dir ? gatesB : gatesF;

    for (int i = tid; i < 64 * 768; i += 256) {
        int r = i / 768, k = i - r * 768;
        int j = jbase + (r >> 2);
        int g = r & 3;
        int korig = k & 255;
        float w = W[((long)(g * Hh + j)) * Hh + korig];
        __nv_bfloat16 hi = __float2bfloat16_rn(w);
        __nv_bfloat16 v;
        if (k >= 256 && k < 512) v = __float2bfloat16_rn(w - __bfloat162float(hi));
        else v = hi;
        Bs[r * BS_STR + k] = v;
    }
    __syncthreads();

    uint32_t aB = smem_u32(As);
    uint32_t bB = smem_u32(Bs);
    int wn = (wid & 3) * 16;
    int kh = wid >> 2;
    float* sdst = kh ? ssum1 : ssum0;

    uint32_t breg[24][4];
#pragma unroll
    for (int si = 0; si < 24; si++) {
        int s = kh * 24 + si;
        int rowB = wn + (lane & 7) + ((lane >> 4) << 3);
        int colB = s * 16 + (((lane >> 3) & 1) << 3);
        ldsm_x4(breg[si][0], breg[si][1], breg[si][2], breg[si][3],
                bB + (rowB * BS_STR + colB) * 2);
    }

    int b_local = tid >> 4, u = tid & 15;
    int bglob = b0 + b_local;
    int j = jbase + u;
    {
        __nv_bfloat16 z = __float2bfloat16_rn(0.f);
        g_hsplit[0][dir][bglob * 512 + j] = z;
        g_hsplit[0][dir][bglob * 512 + 256 + j] = z;
    }
    float c = 0.f;
    grid_sync_grp(grp);

    for (int t = 0; t < Tt; t++) {
        const __nv_bfloat16* hin = g_hsplit[t & 1][dir];
        int tin = dir ? (Tt - 1 - t) : t;

        const int4* src = (const int4*)(hin + (long)b0 * 512);
#pragma unroll
        for (int i = 0; i < 4; i++) {
            int idx = tid + i * 256;
            int row = idx >> 6, ch = idx & 63;
            int4 v = __ldcg(src + row * 64 + ch);
            *(int4*)(As + row * AS_STR + ch * 8) = v;
        }
        {
            int bl = tid >> 4;
            int g  = (tid >> 2) & 3;
            int q  = tid & 3;
            float4 gv = __ldg((const float4*)(gates + ((long)(b0 + bl) * Tt + tin) * G4
                                              + g * Hh + jbase + q * 4));
            gsm[bl * 64 + (q * 4 + 0) * 4 + g] = gv.x;
            gsm[bl * 64 + (q * 4 + 1) * 4 + g] = gv.y;
            gsm[bl * 64 + (q * 4 + 2) * 4 + g] = gv.z;
            gsm[bl * 64 + (q * 4 + 3) * 4 + g] = gv.w;
        }
        __syncthreads();

        float acc0[4] = {0.f, 0.f, 0.f, 0.f};
        float acc1[4] = {0.f, 0.f, 0.f, 0.f};
#pragma unroll
        for (int si = 0; si < 24; si++) {
            int s = kh * 24 + si;
            int kc = (s < 32) ? (s & 15) * 16 : 256 + (s - 32) * 16;
            uint32_t af[4];
            ldsm_x4(af[0], af[1], af[2], af[3],
                    aB + (((lane & 15)) * AS_STR + kc + (lane >> 4) * 8) * 2);
            uint32_t bf0[2] = {breg[si][0], breg[si][1]};
            uint32_t bf1[2] = {breg[si][2], breg[si][3]};
            mma16816(acc0, af, bf0);
            mma16816(acc1, af, bf1);
        }

        {
            int r = lane >> 2, cp = (lane & 3) * 2;
            int m1 = r, m2 = r + 8;
            *(float2*)&sdst[m1 * 64 + wn + cp]     = make_float2(acc0[0], acc0[1]);
            *(float2*)&sdst[m2 * 64 + wn + cp]     = make_float2(acc0[2], acc0[3]);
            *(float2*)&sdst[m1 * 64 + wn + 8 + cp] = make_float2(acc1[0], acc1[1]);
            *(float2*)&sdst[m2 * 64 + wn + 8 + cp] = make_float2(acc1[2], acc1[3]);
        }
        __syncthreads();

        int base = b_local * 64 + u * 4;
        float gi = gsm[base + 0] + ssum0[base + 0] + ssum1[base + 0];
        float gf = gsm[base + 1] + ssum0[base + 1] + ssum1[base + 1];
        float gg = gsm[base + 2] + ssum0[base + 2] + ssum1[base + 2];
        float go = gsm[base + 3] + ssum0[base + 3] + ssum1[base + 3];

        float ii = 1.f / (1.f + expf(-gi));
        float ff = 1.f / (1.f + expf(-gf));
        float tg = tanhf(gg);
        float oo = 1.f / (1.f + expf(-go));
        c = ff * c + ii * tg;
        float h = oo * tanhf(c);

        __nv_bfloat16 hi = __float2bfloat16_rn(h);
        __nv_bfloat16 lo = __float2bfloat16_rn(h - __bfloat162float(hi));
        __nv_bfloat16* hnext = g_hsplit[(t + 1) & 1][dir];
        hnext[bglob * 512 + j] = hi;
        hnext[bglob * 512 + 256 + j] = lo;
        hs_out[((long)bglob * Tt + tin) * TC + dir * Hh + j] = h;

        grid_sync_grp(grp);
    }
}

// ================= misc =================
// write hs1 into catA right half (cols 512..1023) as split flavor A
__global__ void copy_right_split(const float* __restrict__ hs, __nv_bfloat16* __restrict__ catA) {
    long i = (long)blockIdx.x * blockDim.x + threadIdx.x;
    if (i < (long)ROWS * TC) {
        long m = i / TC, j = i % TC;
        float x = hs[i];
        __nv_bfloat16 hi = __float2bfloat16_rn(x);
        __nv_bfloat16 lo = __float2bfloat16_rn(x - __bfloat162float(hi));
        __nv_bfloat16* d = catA + m * 3072 + 512 + j;
        d[0] = hi; d[1024] = hi; d[2048] = lo;
    }
}

__global__ void softmax_rows(const float* __restrict__ S, __nv_bfloat16* __restrict__ dst) {
    const float* row = S + (long)blockIdx.x * Tt;
    __nv_bfloat16* d = dst + (long)blockIdx.x * 1536;
    int tid = threadIdx.x;   // 128
    __shared__ float red[4];

    float mx = -1e30f;
    for (int j = tid; j < Tt; j += 128) mx = fmaxf(mx, row[j]);
#pragma unroll
    for (int o = 16; o; o >>= 1) mx = fmaxf(mx, __shfl_xor_sync(0xffffffffu, mx, o));
    if ((tid & 31) == 0) red[tid >> 5] = mx;
    __syncthreads();
    mx = fmaxf(fmaxf(red[0], red[1]), fmaxf(red[2], red[3]));

    float sum = 0.f;
    float e[4];
#pragma unroll
    for (int q = 0; q < 4; q++) {
        e[q] = expf(row[tid + q * 128] - mx);
        sum += e[q];
    }
#pragma unroll
    for (int o = 16; o; o >>= 1) sum += __shfl_xor_sync(0xffffffffu, sum, o);
    __syncthreads();
    if ((tid & 31) == 0) red[tid >> 5] = sum;
    __syncthreads();
    sum = red[0] + red[1] + red[2] + red[3];
    float inv = 1.f / sum;
#pragma unroll
    for (int q = 0; q < 4; q++) {
        int jj = tid + q * 128;
        float p = e[q] * inv;
        __nv_bfloat16 hi = __float2bfloat16_rn(p);
        __nv_bfloat16 lo = __float2bfloat16_rn(p - __bfloat162float(hi));
        d[jj] = hi; d[512 + jj] = hi; d[1024 + jj] = lo;
    }
}

__global__ void bn_stats(const float* __restrict__ Y, float* __restrict__ mean,
                         float* __restrict__ istd) {
    int ch = blockIdx.x;
    int tid = threadIdx.x;
    __shared__ float rs[8], rq[8];
    float s = 0.f, q = 0.f;
    for (int i = tid; i < Nn * Tt; i += 256) {
        int n = i >> 9, p = i & 511;
        float v = Y[(long)n * 25600 + ch * 512 + p];
        s += v; q += v * v;
    }
#pragma unroll
    for (int o = 16; o; o >>= 1) { s += __shfl_xor_sync(0xffffffffu, s, o); q += __shfl_xor_sync(0xffffffffu, q, o); }
    if ((tid & 31) == 0) { rs[tid >> 5] = s; rq[tid >> 5] = q; }
    __syncthreads();
    if (tid == 0) {
        s = 0.f; q = 0.f;
        for (int w = 0; w < 8; w++) { s += rs[w]; q += rq[w]; }
        float m = s / (float)(Nn * Tt);
        float var = q / (float)(Nn * Tt) - m * m;
        mean[ch] = m;
        istd[ch] = rsqrtf(var + 1e-5f);
    }
}

__global__ void bn_apply(float* __restrict__ Y, const float* __restrict__ mean,
                         const float* __restrict__ istd, const float* __restrict__ gam,
                         const float* __restrict__ bet) {
    long i = (long)blockIdx.x * blockDim.x + threadIdx.x;
    if (i < (long)ROWS * 50) {
        long r = i % 25600;
        int ch = (int)(r >> 9);
        Y[i] = (Y[i] - mean[ch]) * istd[ch] * gam[ch] + bet[ch];
    }
}

template <int K, int N, bool RELU>
__global__ void small_fc(const float* __restrict__ X, const float* __restrict__ W,
                         const float* __restrict__ bias, float* __restrict__ Y) {
    __shared__ float xs[128 * K];
    __shared__ float ws[N * K];
    __shared__ float bs[N];
    int tid = threadIdx.x;
    long m0 = (long)blockIdx.x * 128;
    for (int i = tid; i < N * K; i += 128) ws[i] = W[i];
    for (int i = tid; i < N; i += 128) bs[i] = bias[i];
    for (int i = tid; i < 128 * K; i += 128) xs[i] = X[m0 * K + i];
    __syncthreads();
    long m = m0 + tid;
#pragma unroll
    for (int j = 0; j < N; j++) {
        float acc = bs[j];
#pragma unroll
        for (int k = 0; k < K; k++) acc += xs[tid * K + k] * ws[j * K + k];
        if (RELU) acc = fmaxf(acc, 0.f);
        Y[m * N + j] = acc;
    }
}

// ================= host orchestration =================
extern "C" void kernel_launch(void* const* d_in, const int* in_sizes, int n_in,
                              void* d_out, int out_size)
{
    const float* x     = (const float*)d_in[0];
    const float* wih0f = (const float*)d_in[1];
    const float* whh0f = (const float*)d_in[2];
    const float* b0f   = (const float*)d_in[3];
    const float* wih0b = (const float*)d_in[4];
    const float* whh0b = (const float*)d_in[5];
    const float* b0b   = (const float*)d_in[6];
    const float* wih1f = (const float*)d_in[7];
    const float* whh1f = (const float*)d_in[8];
    const float* b1f   = (const float*)d_in[9];
    const float* wih1b = (const float*)d_in[10];
    const float* whh1b = (const float*)d_in[11];
    const float* b1b   = (const float*)d_in[12];
    const float* fc1w  = (const float*)d_in[13];
    const float* fc1b  = (const float*)d_in[14];
    const float* bng   = (const float*)d_in[15];
    const float* bnb   = (const float*)d_in[16];
    const float* fc2w  = (const float*)d_in[17];
    const float* fc2b  = (const float*)d_in[18];
    const float* fc3w  = (const float*)d_in[19];
    const float* fc3b  = (const float*)d_in[20];
    const float* fc4w  = (const float*)d_in[21];
    const float* fc4b  = (const float*)d_in[22];
    float* out = (float*)d_out;

    float *gF, *gB, *hs0, *hs1, *sc, *f1, *f2, *f3, *mean, *istd;
    __nv_bfloat16 *xA, *w0fB, *w0bB, *w1fB, *w1bB, *hs0A, *hs1A, *hs1B, *hsTB, *attnA, *catA, *fc1wB;
    cudaGetSymbolAddress((void**)&gF,   g_gatesF);
    cudaGetSymbolAddress((void**)&gB,   g_gatesB);
    cudaGetSymbolAddress((void**)&hs0,  g_hs0);
    cudaGetSymbolAddress((void**)&hs1,  g_hs1);
    cudaGetSymbolAddress((void**)&sc,   g_scores);
    cudaGetSymbolAddress((void**)&f1,   g_fc1);
    cudaGetSymbolAddress((void**)&f2,   g_fc2);
    cudaGetSymbolAddress((void**)&f3,   g_fc3);
    cudaGetSymbolAddress((void**)&mean, g_mean);
    cudaGetSymbolAddress((void**)&istd, g_istd);
    cudaGetSymbolAddress((void**)&xA,    g_xA);
    cudaGetSymbolAddress((void**)&w0fB,  g_w0fB);
    cudaGetSymbolAddress((void**)&w0bB,  g_w0bB);
    cudaGetSymbolAddress((void**)&w1fB,  g_w1fB);
    cudaGetSymbolAddress((void**)&w1bB,  g_w1bB);
    cudaGetSymbolAddress((void**)&hs0A,  g_hs0A);
    cudaGetSymbolAddress((void**)&hs1A,  g_hs1A);
    cudaGetSymbolAddress((void**)&hs1B,  g_hs1B);
    cudaGetSymbolAddress((void**)&hsTB,  g_hsTB);
    cudaGetSymbolAddress((void**)&attnA, g_attnA);
    cudaGetSymbolAddress((void**)&catA,  g_catA);
    cudaGetSymbolAddress((void**)&fc1wB, g_fc1wB);

    cudaFuncSetAttribute(lstm_mma, cudaFuncAttributeMaxDynamicSharedMemorySize, LSTM2_SMEM);
    cudaFuncSetAttribute(gemm_mma, cudaFuncAttributeMaxDynamicSharedMemorySize, GEMM_SMEM);

    const int BIGN = 1 << 30;

    // ---- conversions ----
    conv_split<<<(int)(((long)ROWS * Dd + 255) / 256), 256>>>(x, xA, 7, (long)ROWS * Dd, 0);
    conv_split<<<(G4 * Dd + 255) / 256, 256>>>(wih0f, w0fB, 7, (long)G4 * Dd, 1);
    conv_split<<<(G4 * Dd + 255) / 256, 256>>>(wih0b, w0bB, 7, (long)G4 * Dd, 1);
    conv_split<<<(G4 * TC + 255) / 256, 256>>>(wih1f, w1fB, 9, (long)G4 * TC, 1);
    conv_split<<<(G4 * TC + 255) / 256, 256>>>(wih1b, w1bB, 9, (long)G4 * TC, 1);
    conv_split_pad50<<<(128 * 1024 + 255) / 256, 256>>>(fc1w, fc1wB);

    // ---- layer 0 ----
    gemm_mma<<<dim3(8, 256), 256, GEMM_SMEM>>>(xA, w0fB, b0f, gF, nullptr,
                                               384, G4, 0, 0, 0, 0, BIGN, 0);
    gemm_mma<<<dim3(8, 256), 256, GEMM_SMEM>>>(xA, w0bB, b0b, gB, nullptr,
                                               384, G4, 0, 0, 0, 0, BIGN, 0);
    lstm_mma<<<128, 256, LSTM2_SMEM>>>(gF, gB, whh0f, whh0b, hs0);

    // ---- layer 1 ----
    conv_split<<<(int)(((long)ROWS * TC + 255) / 256), 256>>>(hs0, hs0A, 9, (long)ROWS * TC, 0);
    gemm_mma<<<dim3(8, 256), 256, GEMM_SMEM>>>(hs0A, w1fB, b1f, gF, nullptr,
                                               1536, G4, 0, 0, 0, 0, BIGN, 0);
    gemm_mma<<<dim3(8, 256), 256, GEMM_SMEM>>>(hs0A, w1bB, b1b, gB, nullptr,
                                               1536, G4, 0, 0, 0, 0, BIGN, 0);
    lstm_mma<<<128, 256, LSTM2_SMEM>>>(gF, gB, whh1f, whh1b, hs1);

    // ---- attention ----
    conv_split<<<(int)(((long)ROWS * TC + 255) / 256), 256>>>(hs1, hs1A, 9, (long)ROWS * TC, 0);
    conv_split<<<(int)(((long)ROWS * TC + 255) / 256), 256>>>(hs1, hs1B, 9, (long)ROWS * TC, 1);
    transp_convB<<<dim3(16, 16, Nn), dim3(32, 32)>>>(hs1, hsTB);

    long sAB = (long)Tt * 1536;
    gemm_mma<<<dim3(4, 4, Nn), 256, GEMM_SMEM>>>(hs1A, hs1B, nullptr, sc, nullptr,
                                                 1536, Tt, 0, sAB, sAB, (long)Tt * Tt, BIGN, 0);
    softmax_rows<<<Nn * Tt, 128>>>(sc, attnA);
    // context GEMM: writes catA (split flavor A) directly — no fp32 cat, no conv pass
    gemm_mma<<<dim3(4, 4, Nn), 256, GEMM_SMEM>>>(attnA, hsTB, nullptr, nullptr, catA,
                                                 1536, 0, 1024, sAB, sAB, (long)Tt * 1024, BIGN, 0);
    copy_right_split<<<(int)(((long)ROWS * TC + 255) / 256), 256>>>(hs1, catA);

    // ---- head: fc1 via HMMA on catA (N padded 50->128, masked, fused relu) ----
    gemm_mma<<<dim3(1, 256), 256, GEMM_SMEM>>>(catA, fc1wB, fc1b, f1, nullptr,
                                               3072, 50, 0, 0, 0, 0, 50, 1);
    bn_stats<<<50, 256>>>(f1, mean, istd);
    bn_apply<<<(int)(((long)ROWS * 50 + 255) / 256), 256>>>(f1, mean, istd, bng, bnb);
    small_fc<50, 25, true ><<<ROWS / 128, 128>>>(f1, fc2w, fc2b, f2);
    small_fc<25, 10, true ><<<ROWS / 128, 128>>>(f2, fc3w, fc3b, f3);
    small_fc<10, 2,  false><<<ROWS / 128, 128>>>(f3, fc4w, fc4b, out);
}